// round 10
// baseline (speedup 1.0000x reference)
#include <cuda_runtime.h>
#include <cuda_bf16.h>
#include <math.h>
#include <stdint.h>

#define NB     4
#define NPTS   32768
#define CIN    256
#define CINNER 512
#define HEADS  8
#define DHD    64
#define G      32
#define KTOT   6912        // 27 taps * 256 ic
#define NCHUNK 216         // K chunks of 32
#define TM     256         // n tile
#define TN     128         // oc tile
#define STAGES 3
// stage layout (bytes): A_hi @0 (256*80), A_lo @20480, B_hi @40960 (128*80), B_lo @51200
#define STAGE_BYTES 61440

// ---------------- static scratch ----------------
__device__ __nv_bfloat16 g_xhi[(size_t)NB*NPTS*CIN];
__device__ __nv_bfloat16 g_xlo[(size_t)NB*NPTS*CIN];
__device__ __nv_bfloat16 g_whi[(size_t)CINNER*KTOT];   // [oc][tap*256+ic]
__device__ __nv_bfloat16 g_wlo[(size_t)CINNER*KTOT];
__device__ float    g_xp[(size_t)NB*NPTS*CINNER];      // conv output [b][n][inner]
__device__ float    g_l[(size_t)NB*HEADS*G*NPTS];      // logits -> exp in place
__device__ unsigned g_max[NB*HEADS*G];
__device__ float    g_denom_part[NB*HEADS*G*16];
__device__ float    g_denom[NB*HEADS*G];
__device__ float    g_eid_part[(size_t)32*16*G*DHD];
__device__ float    g_eid[(size_t)32*G*DHD];
__device__ float    g_proj[(size_t)NB*256*256];

// ---------------- helpers ----------------
__device__ __forceinline__ unsigned fenc(float f){
    unsigned u = __float_as_uint(f);
    return (u & 0x80000000u) ? ~u : (u | 0x80000000u);
}
__device__ __forceinline__ float fdec(unsigned u){
    u = (u & 0x80000000u) ? (u & 0x7fffffffu) : ~u;
    return __uint_as_float(u);
}
__device__ __forceinline__ uint32_t smem_u32(const void* p){
    uint32_t a;
    asm("{ .reg .u64 t; cvta.to.shared.u64 t, %1; cvt.u32.u64 %0, t; }" : "=r"(a) : "l"(p));
    return a;
}
__device__ __forceinline__ void cp16(uint32_t dst, const void* src, int srcsize){
    asm volatile("cp.async.cg.shared.global [%0], [%1], 16, %2;" :: "r"(dst), "l"(src), "r"(srcsize));
}
__device__ __forceinline__ void ldm4(unsigned* r, uint32_t addr){
    asm volatile("ldmatrix.sync.aligned.m8n8.x4.shared.b16 {%0,%1,%2,%3}, [%4];"
        : "=r"(r[0]), "=r"(r[1]), "=r"(r[2]), "=r"(r[3]) : "r"(addr));
}
__device__ __forceinline__ void mma_bf(float* c, const unsigned* a, unsigned b0, unsigned b1){
    asm volatile("mma.sync.aligned.m16n8k16.row.col.f32.bf16.bf16.f32 "
        "{%0,%1,%2,%3}, {%4,%5,%6,%7}, {%8,%9}, {%0,%1,%2,%3};"
        : "+f"(c[0]), "+f"(c[1]), "+f"(c[2]), "+f"(c[3])
        : "r"(a[0]), "r"(a[1]), "r"(a[2]), "r"(a[3]), "r"(b0), "r"(b1));
}

// ---------------- prep: split x into bf16 hi/lo ----------------
__global__ __launch_bounds__(256) void k_split_x(const float* __restrict__ x){
    size_t i0 = ((size_t)blockIdx.x*256 + threadIdx.x)*8;
    float4 a = *(const float4*)(x + i0);
    float4 b4 = *(const float4*)(x + i0 + 4);
    float v[8] = {a.x,a.y,a.z,a.w,b4.x,b4.y,b4.z,b4.w};
    unsigned hb[8], lb[8];
    #pragma unroll
    for (int j=0;j<8;++j){
        __nv_bfloat16 h = __float2bfloat16(v[j]);
        float r = v[j] - __bfloat162float(h);
        __nv_bfloat16 l = __float2bfloat16(r);
        hb[j] = (unsigned)__bfloat16_as_ushort(h);
        lb[j] = (unsigned)__bfloat16_as_ushort(l);
    }
    uint4 ph = make_uint4(hb[0]|(hb[1]<<16), hb[2]|(hb[3]<<16), hb[4]|(hb[5]<<16), hb[6]|(hb[7]<<16));
    uint4 pl = make_uint4(lb[0]|(lb[1]<<16), lb[2]|(lb[3]<<16), lb[4]|(lb[5]<<16), lb[6]|(lb[7]<<16));
    *(uint4*)(&g_xhi[i0]) = ph;
    *(uint4*)(&g_xlo[i0]) = pl;
}

// ---------------- prep: transpose+split conv_w -> [oc][tap*256+ic] bf16 hi/lo ----------------
__global__ __launch_bounds__(256) void k_split_w(const float* __restrict__ cw){
    int oc = blockIdx.x;
    const float* src = cw + (size_t)oc*KTOT;   // [ic][27]
    for (int j=0;j<27;++j){
        int k = j*256 + threadIdx.x;           // tap=j, ic=tid
        float v = src[threadIdx.x*27 + j];
        __nv_bfloat16 h = __float2bfloat16(v);
        __nv_bfloat16 l = __float2bfloat16(v - __bfloat162float(h));
        g_whi[(size_t)oc*KTOT + k] = h;
        g_wlo[(size_t)oc*KTOT + k] = l;
    }
}

// ---------------- K init: max accumulators ----------------
__global__ void k_init_max(){
    int i = blockIdx.x*256 + threadIdx.x;
    if (i < NB*HEADS*G) g_max[i] = fenc(-3.4e38f);
}

// ---------------- K1: conv as mma.sync bf16 implicit GEMM (split both, 3 MMAs) ----------------
// CTA 256n x 128oc, 16 warps (warp tile 32x64), K chunks of 32, 3-stage cp.async pipeline,
// one __syncthreads per chunk, TERM-MAJOR MMA order (hh x16, hl x16, lh x16) so every
// dependent pair to the same accumulator has 15 independent MMAs between them.
__global__ __launch_bounds__(512,1) void k1_conv_mma(const float* __restrict__ cb){
    extern __shared__ __align__(16) char sm[];
    __shared__ float s_bias[TN];
    const int tid = threadIdx.x;
    const int b = blockIdx.z, n0 = blockIdx.x*TM, oc0 = blockIdx.y*TN;
    if (tid < TN) s_bias[tid] = cb[oc0 + tid];

    const uint32_t s0 = smem_u32(sm);

    // ---- loader roles ----
    const int rowL = tid >> 1, half = tid & 1;
    const int nA = n0 + rowL;
    const int hA = nA >> 10, wA = (nA >> 5) & 31, dA = nA & 31;
    const __nv_bfloat16* xh_row = g_xhi + (size_t)b*NPTS*CIN + (size_t)nA*CIN + half*16;
    const __nv_bfloat16* xl_row = g_xlo + (size_t)b*NPTS*CIN + (size_t)nA*CIN + half*16;
    const uint32_t dstA = s0 + (uint32_t)rowL*80u + (uint32_t)half*32u;
    const int rowB = tid >> 2, q = tid & 3;
    const __nv_bfloat16* wh_row = g_whi + (size_t)(oc0 + rowB)*KTOT + q*8;
    const __nv_bfloat16* wl_row = g_wlo + (size_t)(oc0 + rowB)*KTOT + q*8;
    const uint32_t dstB = s0 + 40960u + (uint32_t)rowB*80u + (uint32_t)q*16u;

    // per-tap geometry, refreshed only when tap changes (every 8 chunks)
    int cur_tap = -1;
    ptrdiff_t tap_off = 0;
    int tap_ss = 0;

    auto load_chunk = [&](int c, int buf){
        uint32_t bo = (uint32_t)buf * STAGE_BYTES;
        int tap = c >> 3;
        if (tap != cur_tap){
            cur_tap = tap;
            int dh = tap/9 - 1, dw = (tap/3)%3 - 1, dd = tap%3 - 1;
            bool valid = ((unsigned)(hA+dh) < 32u) && ((unsigned)(wA+dw) < 32u) && ((unsigned)(dA+dd) < 32u);
            tap_off = valid ? (ptrdiff_t)(dh*1024 + dw*32 + dd)*CIN : 0;
            tap_ss  = valid ? 16 : 0;
        }
        int ic0 = (c & 7) * 32;
        const __nv_bfloat16* sh = xh_row + tap_off + ic0;
        const __nv_bfloat16* sl = xl_row + tap_off + ic0;
        cp16(dstA + bo,           sh,     tap_ss);
        cp16(dstA + bo + 16,      sh + 8, tap_ss);
        cp16(dstA + bo + 20480,   sl,     tap_ss);
        cp16(dstA + bo + 20496,   sl + 8, tap_ss);
        cp16(dstB + bo,           wh_row + c*32, 16);
        cp16(dstB + bo + 10240,   wl_row + c*32, 16);
    };

    // ---- compute role ----
    const int lane = tid & 31, wid = tid >> 5;
    const int wm = (wid & 7) * 32;     // warp m offset (8 x 32 = 256)
    const int wn = (wid >> 3) * 64;    // warp n offset (2 x 64 = 128)
    const uint32_t ldA = s0 + (uint32_t)(wm + (lane & 15))*80u + (uint32_t)((lane >> 4) * 16);
    const uint32_t ldB = s0 + 40960u + (uint32_t)(wn + (lane & 15))*80u + (uint32_t)((lane >> 4) * 16);

    float acc[2][8][4];
    #pragma unroll
    for (int mi=0; mi<2; ++mi)
        #pragma unroll
        for (int ni=0; ni<8; ++ni){
            acc[mi][ni][0]=0.f; acc[mi][ni][1]=0.f; acc[mi][ni][2]=0.f; acc[mi][ni][3]=0.f;
        }

    #pragma unroll
    for (int p=0; p<STAGES-1; ++p){
        load_chunk(p, p);
        asm volatile("cp.async.commit_group;");
    }

    for (int c=0; c<NCHUNK; ++c){
        asm volatile("cp.async.wait_group %0;" :: "n"(STAGES-2));
        __syncthreads();
        int cl = c + STAGES - 1;
        if (cl < NCHUNK) load_chunk(cl, cl % STAGES);
        asm volatile("cp.async.commit_group;");
        uint32_t bo = (uint32_t)(c % STAGES) * STAGE_BYTES;
        #pragma unroll
        for (int ks=0; ks<2; ++ks){
            uint32_t ko = (uint32_t)ks * 32u;   // 16 bf16 = 32 bytes
            unsigned ah[2][4], al[2][4], bh2[4][4], bl2[4][4];
            ldm4(ah[0], ldA + bo + ko);
            ldm4(ah[1], ldA + bo + ko + 16*80);
            #pragma unroll
            for (int nb=0; nb<4; ++nb)
                ldm4(bh2[nb], ldB + bo + ko + nb*16*80);
            ldm4(al[0], ldA + bo + ko + 20480);
            ldm4(al[1], ldA + bo + ko + 20480 + 16*80);
            #pragma unroll
            for (int nb=0; nb<4; ++nb)
                ldm4(bl2[nb], ldB + bo + ko + 10240 + nb*16*80);
            // term-major: hh (16 MMAs), then hl, then lh. Per-accumulator order is
            // still hh -> hl -> lh, so results are bitwise identical to the
            // accumulator-major order; dependent pairs are now 16 issues apart.
            #pragma unroll
            for (int mi=0; mi<2; ++mi)
                #pragma unroll
                for (int nb=0; nb<4; ++nb){
                    mma_bf(acc[mi][2*nb],   ah[mi], bh2[nb][0], bh2[nb][2]);
                    mma_bf(acc[mi][2*nb+1], ah[mi], bh2[nb][1], bh2[nb][3]);
                }
            #pragma unroll
            for (int mi=0; mi<2; ++mi)
                #pragma unroll
                for (int nb=0; nb<4; ++nb){
                    mma_bf(acc[mi][2*nb],   ah[mi], bl2[nb][0], bl2[nb][2]);
                    mma_bf(acc[mi][2*nb+1], ah[mi], bl2[nb][1], bl2[nb][3]);
                }
            #pragma unroll
            for (int mi=0; mi<2; ++mi)
                #pragma unroll
                for (int nb=0; nb<4; ++nb){
                    mma_bf(acc[mi][2*nb],   al[mi], bh2[nb][0], bh2[nb][2]);
                    mma_bf(acc[mi][2*nb+1], al[mi], bh2[nb][1], bh2[nb][3]);
                }
        }
    }

    // ---- epilogue: regs -> gmem with bias ----
    const int gid = lane >> 2, tig = lane & 3;
    #pragma unroll
    for (int mi=0; mi<2; ++mi){
        int row = n0 + wm + mi*16 + gid;
        float* rp = g_xp + ((size_t)b*NPTS + row)*CINNER + oc0;
        #pragma unroll
        for (int ni=0; ni<8; ++ni){
            int lc = wn + ni*8 + tig*2;
            float b0 = s_bias[lc], b1 = s_bias[lc+1];
            float2 v0 = make_float2(acc[mi][ni][0]+b0, acc[mi][ni][1]+b1);
            float2 v1 = make_float2(acc[mi][ni][2]+b0, acc[mi][ni][3]+b1);
            *(float2*)(rp + lc) = v0;
            *(float2*)(rp + lc + 8*CINNER) = v1;
        }
    }
}

// ---------------- K2: temp + scaled logits, block max -> atomicMax ----------------
__global__ __launch_bounds__(256) void k2_logits(const float* __restrict__ slw, const float* __restrict__ slb,
                                                 const float* __restrict__ adw, const float* __restrict__ adb){
    __shared__ float xs[64][68];
    __shared__ float wsm[32][72];
    __shared__ float sb[32];
    __shared__ float temps[64];
    __shared__ float mred[256];
    int tid = threadIdx.x;
    int b = blockIdx.z, h = blockIdx.y, n0 = blockIdx.x*64;
    for (int i=tid; i<2048; i+=256) wsm[i>>6][i&63] = slw[i];
    if (tid < 32) sb[tid] = slb[tid];
    const float* xpb = g_xp + ((size_t)b*NPTS + n0)*CINNER + h*DHD;
    for (int i=tid; i<1024; i+=256){
        int r = i>>4, c4 = i&15;
        *(float4*)&xs[r][c4*4] = *(const float4*)(xpb + (size_t)r*CINNER + c4*4);
    }
    __syncthreads();
    if (tid < 64){
        float s = adb[0];
        #pragma unroll 8
        for (int c=0;c<64;++c) s += xs[tid][c]*adw[c];
        s = fminf(fmaxf(s, -0.4f), 0.4f);
        temps[tid] = 1.0f/(0.5f + s);
    }
    __syncthreads();
    const float LLNE = logf(-logf(1e-6f));
    int g = tid>>3, ns = tid&7;
    float lmax = -3.4e38f;
    float* lout = g_l + ((size_t)(b*HEADS+h)*G + g)*NPTS + n0;
    #pragma unroll
    for (int i=0;i<8;++i){
        int nn = ns + i*8;
        float s = 0.f;
        #pragma unroll
        for (int c4=0;c4<16;++c4){
            float4 xv = *(const float4*)&xs[nn][c4*4];
            float4 wv = *(const float4*)&wsm[g][c4*4];
            s += xv.x*wv.x + xv.y*wv.y + xv.z*wv.z + xv.w*wv.w;
        }
        float l = (s + sb[g] - LLNE)*temps[nn];
        lout[nn] = l;
        lmax = fmaxf(lmax, l);
    }
    mred[tid] = lmax;
    __syncthreads();
    if (ns == 0){
        float m = mred[tid];
        #pragma unroll
        for (int j=1;j<8;++j) m = fmaxf(m, mred[tid+j]);
        atomicMax(&g_max[(b*HEADS+h)*G + g], fenc(m));
    }
}

// ---------------- K3: exp in place + partial denom sums ----------------
__global__ __launch_bounds__(256) void k3_exp(){
    __shared__ float red[256];
    int tid = threadIdx.x;
    int chunk = blockIdx.x, bhg = blockIdx.y;
    float m = fdec(g_max[bhg]);
    size_t base = (size_t)bhg*NPTS + (size_t)chunk*2048;
    float s = 0.f;
    #pragma unroll
    for (int i=0;i<8;++i){
        size_t idx = base + tid + i*256;
        float e = expf(g_l[idx] - m);
        g_l[idx] = e;
        s += e;
    }
    red[tid]=s; __syncthreads();
    for (int off=128; off>0; off>>=1){ if (tid<off) red[tid]+=red[tid+off]; __syncthreads(); }
    if (tid==0) g_denom_part[bhg*16 + chunk] = red[0];
}
__global__ void k3b_denom(){
    int i = blockIdx.x*256 + threadIdx.x;   // bhg
    float s = 0.f;
    #pragma unroll
    for (int c=0;c<16;++c) s += g_denom_part[i*16+c];
    g_denom[i] = s;
}

// ---------------- K5: eid partials (split-K GEMM, deterministic) ----------------
__global__ __launch_bounds__(256) void k5_eid_part(){
    __shared__ float xs[64][64];
    __shared__ float es[32][68];
    int tid = threadIdx.x;
    int chunk = blockIdx.x, bh = blockIdx.y;
    int b = bh>>3, h = bh&7;
    int g = tid>>3, cb2 = (tid&7)*8;
    float acc[8] = {0.f,0.f,0.f,0.f,0.f,0.f,0.f,0.f};
    for (int t=0; t<32; ++t){
        int n0 = chunk*2048 + t*64;
        __syncthreads();
        const float* xpb = g_xp + ((size_t)b*NPTS + n0)*CINNER + h*DHD;
        #pragma unroll
        for (int i=0;i<4;++i){
            int idx = tid + i*256;
            int r = idx>>4, c4 = idx&15;
            *(float4*)&xs[r][c4*4] = *(const float4*)(xpb + (size_t)r*CINNER + c4*4);
        }
        const float* lb = g_l + ((size_t)bh*G)*NPTS + n0;
        #pragma unroll
        for (int i=0;i<2;++i){
            int idx = tid + i*256;
            int r = idx>>4, c4 = idx&15;
            *(float4*)&es[r][c4*4] = *(const float4*)(lb + (size_t)r*NPTS + c4*4);
        }
        __syncthreads();
        #pragma unroll 4
        for (int n=0;n<64;++n){
            float ev = es[g][n];
            float4 x0 = *(const float4*)&xs[n][cb2];
            float4 x1 = *(const float4*)&xs[n][cb2+4];
            acc[0]+=ev*x0.x; acc[1]+=ev*x0.y; acc[2]+=ev*x0.z; acc[3]+=ev*x0.w;
            acc[4]+=ev*x1.x; acc[5]+=ev*x1.y; acc[6]+=ev*x1.z; acc[7]+=ev*x1.w;
        }
    }
    float* dst = g_eid_part + (size_t)(bh*16+chunk)*2048 + g*64 + cb2;
    #pragma unroll
    for (int j=0;j<8;++j) dst[j] = acc[j];
}
__global__ void k5b_eid(){
    int bh = blockIdx.x;
    int tid = threadIdx.x;
    #pragma unroll
    for (int j=0;j<8;++j){
        int s = tid + j*256;
        float acc = 0.f;
        #pragma unroll
        for (int ch=0; ch<16; ++ch) acc += g_eid_part[(size_t)(bh*16+ch)*2048 + s];
        float dn = g_denom[bh*G + (s>>6)];
        g_eid[(size_t)bh*2048 + s] = acc / (dn * (1.0f + 1e-5f));
    }
}

// ---------------- K6: proj[b][hg][o] = (eid @ out_w_slice^T) / denom ----------------
__global__ __launch_bounds__(256) void k6_proj(const float* __restrict__ ow){
    __shared__ float ev[64];
    int b = blockIdx.y, k = blockIdx.x;
    int h = k>>5, g = k&31;
    int tid = threadIdx.x;    // = o
    if (tid < 64) ev[tid] = g_eid[(size_t)(b*8+h)*2048 + g*64 + tid];
    __syncthreads();
    const float* wr = ow + (size_t)tid*CINNER + h*DHD;
    float s = 0.f;
    #pragma unroll 8
    for (int c=0;c<64;++c) s += ev[c]*wr[c];
    g_proj[((size_t)b*256 + k)*256 + tid] = s / g_denom[(b*8+h)*G + g];
}

// ---------------- K7: final = E^T(256,N) x proj(256,256) + out_b ----------------
__global__ __launch_bounds__(256) void k7_final(const float* __restrict__ ob, float* __restrict__ out){
    __shared__ float as2[16][132];
    __shared__ float ps[16][68];
    int tid = threadIdx.x;
    int b = blockIdx.z, n0 = blockIdx.x*128, o0 = blockIdx.y*64;
    int mf = tid&15, of = tid>>4;
    float acc[8][4];
    #pragma unroll
    for (int i=0;i<8;++i){ acc[i][0]=0.f; acc[i][1]=0.f; acc[i][2]=0.f; acc[i][3]=0.f; }
    for (int kt=0; kt<16; ++kt){
        int k0 = kt*16;
        __syncthreads();
        #pragma unroll
        for (int i=0;i<2;++i){
            int idx = tid + i*256;
            int r = idx>>5, c4 = idx&31;
            *(float4*)&as2[r][c4*4] = *(const float4*)(g_l + ((size_t)b*256 + k0 + r)*NPTS + n0 + c4*4);
        }
        {
            int r = tid>>4, c4 = tid&15;
            *(float4*)&ps[r][c4*4] = *(const float4*)(g_proj + ((size_t)b*256 + k0 + r)*256 + o0 + c4*4);
        }
        __syncthreads();
        #pragma unroll
        for (int kk=0;kk<16;++kk){
            float4 a0 = *(const float4*)&as2[kk][mf*8];
            float4 a1 = *(const float4*)&as2[kk][mf*8+4];
            float4 bv = *(const float4*)&ps[kk][of*4];
            float av[8]={a0.x,a0.y,a0.z,a0.w,a1.x,a1.y,a1.z,a1.w};
            #pragma unroll
            for (int i=0;i<8;++i){
                acc[i][0] += av[i]*bv.x;
                acc[i][1] += av[i]*bv.y;
                acc[i][2] += av[i]*bv.z;
                acc[i][3] += av[i]*bv.w;
            }
        }
    }
    float obv[4];
    #pragma unroll
    for (int j=0;j<4;++j) obv[j] = ob[o0 + of*4 + j];
    #pragma unroll
    for (int i=0;i<8;++i){
        int n = n0 + mf*8 + i;
        *(float4*)(out + ((size_t)b*NPTS + n)*256 + o0 + of*4) =
            make_float4(acc[i][0]+obv[0], acc[i][1]+obv[1], acc[i][2]+obv[2], acc[i][3]+obv[3]);
    }
}

// ---------------- launch ----------------
extern "C" void kernel_launch(void* const* d_in, const int* in_sizes, int n_in,
                              void* d_out, int out_size){
    const float* x   = (const float*)d_in[0];
    const float* cw  = (const float*)d_in[1];
    const float* cb  = (const float*)d_in[2];
    const float* slw = (const float*)d_in[3];
    const float* slb = (const float*)d_in[4];
    const float* adw = (const float*)d_in[5];
    const float* adb = (const float*)d_in[6];
    const float* ow  = (const float*)d_in[7];
    const float* ob  = (const float*)d_in[8];
    float* out = (float*)d_out;

    cudaFuncSetAttribute(k1_conv_mma, cudaFuncAttributeMaxDynamicSharedMemorySize, STAGES*STAGE_BYTES);

    k_split_x  <<<16384, 256>>>(x);
    k_split_w  <<<512, 256>>>(cw);
    k_init_max <<<4, 256>>>();
    k1_conv_mma<<<dim3(128,4,4), 512, STAGES*STAGE_BYTES>>>(cb);   // launch idx 3 -> profiled
    k2_logits  <<<dim3(512,8,4), 256>>>(slw, slb, adw, adb);
    k3_exp     <<<dim3(16,1024), 256>>>();
    k3b_denom  <<<4, 256>>>();
    k5_eid_part<<<dim3(16,32), 256>>>();
    k5b_eid    <<<32, 256>>>();
    k6_proj    <<<dim3(256,4), 256>>>(ow);
    k7_final   <<<dim3(256,4,4), 256>>>(ob, out);
}

// round 11
// speedup vs baseline: 1.0236x; 1.0236x over previous
#include <cuda_runtime.h>
#include <cuda_bf16.h>
#include <math.h>
#include <stdint.h>

#define NB     4
#define NPTS   32768
#define CIN    256
#define CINNER 512
#define HEADS  8
#define DHD    64
#define G      32
#define KTOT   6912        // 27 taps * 256 ic
#define NCHUNK 216         // K chunks of 32
#define TM     128         // n tile
#define TN     128         // oc tile
#define STAGES 2
// stage layout (bytes): A_hi @0 (128*80), A_lo @10240, B_hi @20480 (128*80), B_lo @30720
#define STAGE_BYTES 40960

// ---------------- static scratch ----------------
__device__ __nv_bfloat16 g_xhi[(size_t)NB*NPTS*CIN];
__device__ __nv_bfloat16 g_xlo[(size_t)NB*NPTS*CIN];
__device__ __nv_bfloat16 g_whi[(size_t)CINNER*KTOT];   // [oc][tap*256+ic]
__device__ __nv_bfloat16 g_wlo[(size_t)CINNER*KTOT];
__device__ float    g_xp[(size_t)NB*NPTS*CINNER];      // conv output [b][n][inner]
__device__ float    g_l[(size_t)NB*HEADS*G*NPTS];      // logits -> exp in place
__device__ unsigned g_max[NB*HEADS*G];
__device__ float    g_denom_part[NB*HEADS*G*16];
__device__ float    g_denom[NB*HEADS*G];
__device__ float    g_eid_part[(size_t)32*16*G*DHD];
__device__ float    g_eid[(size_t)32*G*DHD];
__device__ float    g_proj[(size_t)NB*256*256];

// ---------------- helpers ----------------
__device__ __forceinline__ unsigned fenc(float f){
    unsigned u = __float_as_uint(f);
    return (u & 0x80000000u) ? ~u : (u | 0x80000000u);
}
__device__ __forceinline__ float fdec(unsigned u){
    u = (u & 0x80000000u) ? (u & 0x7fffffffu) : ~u;
    return __uint_as_float(u);
}
__device__ __forceinline__ uint32_t smem_u32(const void* p){
    uint32_t a;
    asm("{ .reg .u64 t; cvta.to.shared.u64 t, %1; cvt.u32.u64 %0, t; }" : "=r"(a) : "l"(p));
    return a;
}
__device__ __forceinline__ void cp16(uint32_t dst, const void* src, int srcsize){
    asm volatile("cp.async.cg.shared.global [%0], [%1], 16, %2;" :: "r"(dst), "l"(src), "r"(srcsize));
}
__device__ __forceinline__ void ldm4(unsigned* r, uint32_t addr){
    asm volatile("ldmatrix.sync.aligned.m8n8.x4.shared.b16 {%0,%1,%2,%3}, [%4];"
        : "=r"(r[0]), "=r"(r[1]), "=r"(r[2]), "=r"(r[3]) : "r"(addr));
}
__device__ __forceinline__ void mma_bf(float* c, const unsigned* a, unsigned b0, unsigned b1){
    asm volatile("mma.sync.aligned.m16n8k16.row.col.f32.bf16.bf16.f32 "
        "{%0,%1,%2,%3}, {%4,%5,%6,%7}, {%8,%9}, {%0,%1,%2,%3};"
        : "+f"(c[0]), "+f"(c[1]), "+f"(c[2]), "+f"(c[3])
        : "r"(a[0]), "r"(a[1]), "r"(a[2]), "r"(a[3]), "r"(b0), "r"(b1));
}

// ---------------- prep: split x into bf16 hi/lo ----------------
__global__ __launch_bounds__(256) void k_split_x(const float* __restrict__ x){
    size_t i0 = ((size_t)blockIdx.x*256 + threadIdx.x)*8;
    float4 a = *(const float4*)(x + i0);
    float4 b4 = *(const float4*)(x + i0 + 4);
    float v[8] = {a.x,a.y,a.z,a.w,b4.x,b4.y,b4.z,b4.w};
    unsigned hb[8], lb[8];
    #pragma unroll
    for (int j=0;j<8;++j){
        __nv_bfloat16 h = __float2bfloat16(v[j]);
        float r = v[j] - __bfloat162float(h);
        __nv_bfloat16 l = __float2bfloat16(r);
        hb[j] = (unsigned)__bfloat16_as_ushort(h);
        lb[j] = (unsigned)__bfloat16_as_ushort(l);
    }
    uint4 ph = make_uint4(hb[0]|(hb[1]<<16), hb[2]|(hb[3]<<16), hb[4]|(hb[5]<<16), hb[6]|(hb[7]<<16));
    uint4 pl = make_uint4(lb[0]|(lb[1]<<16), lb[2]|(lb[3]<<16), lb[4]|(lb[5]<<16), lb[6]|(lb[7]<<16));
    *(uint4*)(&g_xhi[i0]) = ph;
    *(uint4*)(&g_xlo[i0]) = pl;
}

// ---------------- prep: transpose+split conv_w -> [oc][tap*256+ic] bf16 hi/lo ----------------
__global__ __launch_bounds__(256) void k_split_w(const float* __restrict__ cw){
    int oc = blockIdx.x;
    const float* src = cw + (size_t)oc*KTOT;   // [ic][27]
    for (int j=0;j<27;++j){
        int k = j*256 + threadIdx.x;           // tap=j, ic=tid
        float v = src[threadIdx.x*27 + j];
        __nv_bfloat16 h = __float2bfloat16(v);
        __nv_bfloat16 l = __float2bfloat16(v - __bfloat162float(h));
        g_whi[(size_t)oc*KTOT + k] = h;
        g_wlo[(size_t)oc*KTOT + k] = l;
    }
}

// ---------------- K init: max accumulators ----------------
__global__ void k_init_max(){
    int i = blockIdx.x*256 + threadIdx.x;
    if (i < NB*HEADS*G) g_max[i] = fenc(-3.4e38f);
}

// ---------------- K1: conv as mma.sync bf16 implicit GEMM (split both, 3 MMAs) ----------------
// CTA 128n x 128oc, 8 warps (warp tile 32x64), 2-stage pipeline, 2 CTAs/SM.
// Two independent CTAs per SM desynchronize chunk phases: one CTA's MMA burst
// covers the other's sync + ldmatrix window.
__global__ __launch_bounds__(256,2) void k1_conv_mma(const float* __restrict__ cb){
    extern __shared__ __align__(16) char sm[];
    __shared__ float s_bias[TN];
    const int tid = threadIdx.x;
    const int b = blockIdx.z, n0 = blockIdx.x*TM, oc0 = blockIdx.y*TN;
    if (tid < TN) s_bias[tid] = cb[oc0 + tid];

    const uint32_t s0 = smem_u32(sm);

    // ---- loader roles: 2 threads per row for both A (128 n-rows) and B (128 oc-rows)
    const int rowL = tid >> 1, half = tid & 1;
    const int nA = n0 + rowL;
    const int hA = nA >> 10, wA = (nA >> 5) & 31, dA = nA & 31;
    const __nv_bfloat16* xh_row = g_xhi + (size_t)b*NPTS*CIN + (size_t)nA*CIN + half*16;
    const __nv_bfloat16* xl_row = g_xlo + (size_t)b*NPTS*CIN + (size_t)nA*CIN + half*16;
    const uint32_t dstA = s0 + (uint32_t)rowL*80u + (uint32_t)half*32u;
    const __nv_bfloat16* wh_row = g_whi + (size_t)(oc0 + rowL)*KTOT + half*16;
    const __nv_bfloat16* wl_row = g_wlo + (size_t)(oc0 + rowL)*KTOT + half*16;
    const uint32_t dstB = s0 + 20480u + (uint32_t)rowL*80u + (uint32_t)half*32u;

    // per-tap geometry, refreshed only when tap changes (every 8 chunks)
    int cur_tap = -1;
    ptrdiff_t tap_off = 0;
    int tap_ss = 0;

    auto load_chunk = [&](int c, int buf){
        uint32_t bo = (uint32_t)buf * STAGE_BYTES;
        int tap = c >> 3;
        if (tap != cur_tap){
            cur_tap = tap;
            int dh = tap/9 - 1, dw = (tap/3)%3 - 1, dd = tap%3 - 1;
            bool valid = ((unsigned)(hA+dh) < 32u) && ((unsigned)(wA+dw) < 32u) && ((unsigned)(dA+dd) < 32u);
            tap_off = valid ? (ptrdiff_t)(dh*1024 + dw*32 + dd)*CIN : 0;
            tap_ss  = valid ? 16 : 0;
        }
        int ic0 = (c & 7) * 32;
        const __nv_bfloat16* sh = xh_row + tap_off + ic0;
        const __nv_bfloat16* sl = xl_row + tap_off + ic0;
        cp16(dstA + bo,           sh,     tap_ss);
        cp16(dstA + bo + 16,      sh + 8, tap_ss);
        cp16(dstA + bo + 10240,   sl,     tap_ss);
        cp16(dstA + bo + 10256,   sl + 8, tap_ss);
        const __nv_bfloat16* bh = wh_row + (size_t)c*32;
        const __nv_bfloat16* bl = wl_row + (size_t)c*32;
        cp16(dstB + bo,           bh,     16);
        cp16(dstB + bo + 16,      bh + 8, 16);
        cp16(dstB + bo + 10240,   bl,     16);
        cp16(dstB + bo + 10256,   bl + 8, 16);
    };

    // ---- compute role: 8 warps, wm in {0,32,64,96}, wn in {0,64}
    const int lane = tid & 31, wid = tid >> 5;
    const int wm = (wid & 3) * 32;
    const int wn = (wid >> 2) * 64;
    const uint32_t ldA = s0 + (uint32_t)(wm + (lane & 15))*80u + (uint32_t)((lane >> 4) * 16);
    const uint32_t ldB = s0 + 20480u + (uint32_t)(wn + (lane & 15))*80u + (uint32_t)((lane >> 4) * 16);

    float acc[2][8][4];
    #pragma unroll
    for (int mi=0; mi<2; ++mi)
        #pragma unroll
        for (int ni=0; ni<8; ++ni){
            acc[mi][ni][0]=0.f; acc[mi][ni][1]=0.f; acc[mi][ni][2]=0.f; acc[mi][ni][3]=0.f;
        }

    load_chunk(0, 0);
    asm volatile("cp.async.commit_group;");

    for (int c=0; c<NCHUNK; ++c){
        asm volatile("cp.async.wait_group 0;");
        __syncthreads();
        // prefetch next chunk into the other buffer (its readers finished at c-1,
        // proven by the sync all threads just passed)
        if (c + 1 < NCHUNK) load_chunk(c + 1, (c + 1) & 1);
        asm volatile("cp.async.commit_group;");
        uint32_t bo = (uint32_t)(c & 1) * STAGE_BYTES;
        #pragma unroll
        for (int ks=0; ks<2; ++ks){
            uint32_t ko = (uint32_t)ks * 32u;   // 16 bf16 = 32 bytes
            unsigned ah[2][4], al[2][4], bh2[4][4], bl2[4][4];
            ldm4(ah[0], ldA + bo + ko);
            ldm4(ah[1], ldA + bo + ko + 16*80);
            #pragma unroll
            for (int nb=0; nb<4; ++nb)
                ldm4(bh2[nb], ldB + bo + ko + nb*16*80);
            ldm4(al[0], ldA + bo + ko + 10240);
            ldm4(al[1], ldA + bo + ko + 10240 + 16*80);
            #pragma unroll
            for (int nb=0; nb<4; ++nb)
                ldm4(bl2[nb], ldB + bo + ko + 10240 + nb*16*80);
            // per-accumulator order hh -> hl -> lh (bitwise-stable vs prior rounds)
            #pragma unroll
            for (int mi=0; mi<2; ++mi)
                #pragma unroll
                for (int nb=0; nb<4; ++nb){
                    mma_bf(acc[mi][2*nb],   ah[mi], bh2[nb][0], bh2[nb][2]);
                    mma_bf(acc[mi][2*nb+1], ah[mi], bh2[nb][1], bh2[nb][3]);
                }
            #pragma unroll
            for (int mi=0; mi<2; ++mi)
                #pragma unroll
                for (int nb=0; nb<4; ++nb){
                    mma_bf(acc[mi][2*nb],   ah[mi], bl2[nb][0], bl2[nb][2]);
                    mma_bf(acc[mi][2*nb+1], ah[mi], bl2[nb][1], bl2[nb][3]);
                }
            #pragma unroll
            for (int mi=0; mi<2; ++mi)
                #pragma unroll
                for (int nb=0; nb<4; ++nb){
                    mma_bf(acc[mi][2*nb],   al[mi], bh2[nb][0], bh2[nb][2]);
                    mma_bf(acc[mi][2*nb+1], al[mi], bh2[nb][1], bh2[nb][3]);
                }
        }
    }

    // ---- epilogue: regs -> gmem with bias ----
    const int gid = lane >> 2, tig = lane & 3;
    #pragma unroll
    for (int mi=0; mi<2; ++mi){
        int row = n0 + wm + mi*16 + gid;
        float* rp = g_xp + ((size_t)b*NPTS + row)*CINNER + oc0;
        #pragma unroll
        for (int ni=0; ni<8; ++ni){
            int lc = wn + ni*8 + tig*2;
            float b0 = s_bias[lc], b1 = s_bias[lc+1];
            float2 v0 = make_float2(acc[mi][ni][0]+b0, acc[mi][ni][1]+b1);
            float2 v1 = make_float2(acc[mi][ni][2]+b0, acc[mi][ni][3]+b1);
            *(float2*)(rp + lc) = v0;
            *(float2*)(rp + lc + 8*CINNER) = v1;
        }
    }
}

// ---------------- K2: temp + scaled logits, block max -> atomicMax ----------------
__global__ __launch_bounds__(256) void k2_logits(const float* __restrict__ slw, const float* __restrict__ slb,
                                                 const float* __restrict__ adw, const float* __restrict__ adb){
    __shared__ float xs[64][68];
    __shared__ float wsm[32][72];
    __shared__ float sb[32];
    __shared__ float temps[64];
    __shared__ float mred[256];
    int tid = threadIdx.x;
    int b = blockIdx.z, h = blockIdx.y, n0 = blockIdx.x*64;
    for (int i=tid; i<2048; i+=256) wsm[i>>6][i&63] = slw[i];
    if (tid < 32) sb[tid] = slb[tid];
    const float* xpb = g_xp + ((size_t)b*NPTS + n0)*CINNER + h*DHD;
    for (int i=tid; i<1024; i+=256){
        int r = i>>4, c4 = i&15;
        *(float4*)&xs[r][c4*4] = *(const float4*)(xpb + (size_t)r*CINNER + c4*4);
    }
    __syncthreads();
    if (tid < 64){
        float s = adb[0];
        #pragma unroll 8
        for (int c=0;c<64;++c) s += xs[tid][c]*adw[c];
        s = fminf(fmaxf(s, -0.4f), 0.4f);
        temps[tid] = 1.0f/(0.5f + s);
    }
    __syncthreads();
    const float LLNE = logf(-logf(1e-6f));
    int g = tid>>3, ns = tid&7;
    float lmax = -3.4e38f;
    float* lout = g_l + ((size_t)(b*HEADS+h)*G + g)*NPTS + n0;
    #pragma unroll
    for (int i=0;i<8;++i){
        int nn = ns + i*8;
        float s = 0.f;
        #pragma unroll
        for (int c4=0;c4<16;++c4){
            float4 xv = *(const float4*)&xs[nn][c4*4];
            float4 wv = *(const float4*)&wsm[g][c4*4];
            s += xv.x*wv.x + xv.y*wv.y + xv.z*wv.z + xv.w*wv.w;
        }
        float l = (s + sb[g] - LLNE)*temps[nn];
        lout[nn] = l;
        lmax = fmaxf(lmax, l);
    }
    mred[tid] = lmax;
    __syncthreads();
    if (ns == 0){
        float m = mred[tid];
        #pragma unroll
        for (int j=1;j<8;++j) m = fmaxf(m, mred[tid+j]);
        atomicMax(&g_max[(b*HEADS+h)*G + g], fenc(m));
    }
}

// ---------------- K3: exp in place + partial denom sums ----------------
__global__ __launch_bounds__(256) void k3_exp(){
    __shared__ float red[256];
    int tid = threadIdx.x;
    int chunk = blockIdx.x, bhg = blockIdx.y;
    float m = fdec(g_max[bhg]);
    size_t base = (size_t)bhg*NPTS + (size_t)chunk*2048;
    float s = 0.f;
    #pragma unroll
    for (int i=0;i<8;++i){
        size_t idx = base + tid + i*256;
        float e = expf(g_l[idx] - m);
        g_l[idx] = e;
        s += e;
    }
    red[tid]=s; __syncthreads();
    for (int off=128; off>0; off>>=1){ if (tid<off) red[tid]+=red[tid+off]; __syncthreads(); }
    if (tid==0) g_denom_part[bhg*16 + chunk] = red[0];
}
__global__ void k3b_denom(){
    int i = blockIdx.x*256 + threadIdx.x;   // bhg
    float s = 0.f;
    #pragma unroll
    for (int c=0;c<16;++c) s += g_denom_part[i*16+c];
    g_denom[i] = s;
}

// ---------------- K5: eid partials (split-K GEMM, deterministic) ----------------
__global__ __launch_bounds__(256) void k5_eid_part(){
    __shared__ float xs[64][64];
    __shared__ float es[32][68];
    int tid = threadIdx.x;
    int chunk = blockIdx.x, bh = blockIdx.y;
    int b = bh>>3, h = bh&7;
    int g = tid>>3, cb2 = (tid&7)*8;
    float acc[8] = {0.f,0.f,0.f,0.f,0.f,0.f,0.f,0.f};
    for (int t=0; t<32; ++t){
        int n0 = chunk*2048 + t*64;
        __syncthreads();
        const float* xpb = g_xp + ((size_t)b*NPTS + n0)*CINNER + h*DHD;
        #pragma unroll
        for (int i=0;i<4;++i){
            int idx = tid + i*256;
            int r = idx>>4, c4 = idx&15;
            *(float4*)&xs[r][c4*4] = *(const float4*)(xpb + (size_t)r*CINNER + c4*4);
        }
        const float* lb = g_l + ((size_t)bh*G)*NPTS + n0;
        #pragma unroll
        for (int i=0;i<2;++i){
            int idx = tid + i*256;
            int r = idx>>4, c4 = idx&15;
            *(float4*)&es[r][c4*4] = *(const float4*)(lb + (size_t)r*NPTS + c4*4);
        }
        __syncthreads();
        #pragma unroll 4
        for (int n=0;n<64;++n){
            float ev = es[g][n];
            float4 x0 = *(const float4*)&xs[n][cb2];
            float4 x1 = *(const float4*)&xs[n][cb2+4];
            acc[0]+=ev*x0.x; acc[1]+=ev*x0.y; acc[2]+=ev*x0.z; acc[3]+=ev*x0.w;
            acc[4]+=ev*x1.x; acc[5]+=ev*x1.y; acc[6]+=ev*x1.z; acc[7]+=ev*x1.w;
        }
    }
    float* dst = g_eid_part + (size_t)(bh*16+chunk)*2048 + g*64 + cb2;
    #pragma unroll
    for (int j=0;j<8;++j) dst[j] = acc[j];
}
__global__ void k5b_eid(){
    int bh = blockIdx.x;
    int tid = threadIdx.x;
    #pragma unroll
    for (int j=0;j<8;++j){
        int s = tid + j*256;
        float acc = 0.f;
        #pragma unroll
        for (int ch=0; ch<16; ++ch) acc += g_eid_part[(size_t)(bh*16+ch)*2048 + s];
        float dn = g_denom[bh*G + (s>>6)];
        g_eid[(size_t)bh*2048 + s] = acc / (dn * (1.0f + 1e-5f));
    }
}

// ---------------- K6: proj[b][hg][o] = (eid @ out_w_slice^T) / denom ----------------
__global__ __launch_bounds__(256) void k6_proj(const float* __restrict__ ow){
    __shared__ float ev[64];
    int b = blockIdx.y, k = blockIdx.x;
    int h = k>>5, g = k&31;
    int tid = threadIdx.x;    // = o
    if (tid < 64) ev[tid] = g_eid[(size_t)(b*8+h)*2048 + g*64 + tid];
    __syncthreads();
    const float* wr = ow + (size_t)tid*CINNER + h*DHD;
    float s = 0.f;
    #pragma unroll 8
    for (int c=0;c<64;++c) s += ev[c]*wr[c];
    g_proj[((size_t)b*256 + k)*256 + tid] = s / g_denom[(b*8+h)*G + g];
}

// ---------------- K7: final = E^T(256,N) x proj(256,256) + out_b ----------------
__global__ __launch_bounds__(256) void k7_final(const float* __restrict__ ob, float* __restrict__ out){
    __shared__ float as2[16][132];
    __shared__ float ps[16][68];
    int tid = threadIdx.x;
    int b = blockIdx.z, n0 = blockIdx.x*128, o0 = blockIdx.y*64;
    int mf = tid&15, of = tid>>4;
    float acc[8][4];
    #pragma unroll
    for (int i=0;i<8;++i){ acc[i][0]=0.f; acc[i][1]=0.f; acc[i][2]=0.f; acc[i][3]=0.f; }
    for (int kt=0; kt<16; ++kt){
        int k0 = kt*16;
        __syncthreads();
        #pragma unroll
        for (int i=0;i<2;++i){
            int idx = tid + i*256;
            int r = idx>>5, c4 = idx&31;
            *(float4*)&as2[r][c4*4] = *(const float4*)(g_l + ((size_t)b*256 + k0 + r)*NPTS + n0 + c4*4);
        }
        {
            int r = tid>>4, c4 = tid&15;
            *(float4*)&ps[r][c4*4] = *(const float4*)(g_proj + ((size_t)b*256 + k0 + r)*256 + o0 + c4*4);
        }
        __syncthreads();
        #pragma unroll
        for (int kk=0;kk<16;++kk){
            float4 a0 = *(const float4*)&as2[kk][mf*8];
            float4 a1 = *(const float4*)&as2[kk][mf*8+4];
            float4 bv = *(const float4*)&ps[kk][of*4];
            float av[8]={a0.x,a0.y,a0.z,a0.w,a1.x,a1.y,a1.z,a1.w};
            #pragma unroll
            for (int i=0;i<8;++i){
                acc[i][0] += av[i]*bv.x;
                acc[i][1] += av[i]*bv.y;
                acc[i][2] += av[i]*bv.z;
                acc[i][3] += av[i]*bv.w;
            }
        }
    }
    float obv[4];
    #pragma unroll
    for (int j=0;j<4;++j) obv[j] = ob[o0 + of*4 + j];
    #pragma unroll
    for (int i=0;i<8;++i){
        int n = n0 + mf*8 + i;
        *(float4*)(out + ((size_t)b*NPTS + n)*256 + o0 + of*4) =
            make_float4(acc[i][0]+obv[0], acc[i][1]+obv[1], acc[i][2]+obv[2], acc[i][3]+obv[3]);
    }
}

// ---------------- launch ----------------
extern "C" void kernel_launch(void* const* d_in, const int* in_sizes, int n_in,
                              void* d_out, int out_size){
    const float* x   = (const float*)d_in[0];
    const float* cw  = (const float*)d_in[1];
    const float* cb  = (const float*)d_in[2];
    const float* slw = (const float*)d_in[3];
    const float* slb = (const float*)d_in[4];
    const float* adw = (const float*)d_in[5];
    const float* adb = (const float*)d_in[6];
    const float* ow  = (const float*)d_in[7];
    const float* ob  = (const float*)d_in[8];
    float* out = (float*)d_out;

    cudaFuncSetAttribute(k1_conv_mma, cudaFuncAttributeMaxDynamicSharedMemorySize, STAGES*STAGE_BYTES);

    k_split_x  <<<16384, 256>>>(x);
    k_split_w  <<<512, 256>>>(cw);
    k_init_max <<<4, 256>>>();
    k1_conv_mma<<<dim3(256,4,4), 256, STAGES*STAGE_BYTES>>>(cb);   // launch idx 3 -> profiled
    k2_logits  <<<dim3(512,8,4), 256>>>(slw, slb, adw, adb);
    k3_exp     <<<dim3(16,1024), 256>>>();
    k3b_denom  <<<4, 256>>>();
    k5_eid_part<<<dim3(16,32), 256>>>();
    k5b_eid    <<<32, 256>>>();
    k6_proj    <<<dim3(256,4), 256>>>(ow);
    k7_final   <<<dim3(256,4,4), 256>>>(ob, out);
}

// round 13
// speedup vs baseline: 1.0874x; 1.0624x over previous
#include <cuda_runtime.h>
#include <cuda_bf16.h>
#include <math.h>
#include <stdint.h>

#define NB     4
#define NPTS   32768
#define CIN    256
#define CINNER 512
#define HEADS  8
#define DHD    64
#define G      32
#define KTOT   6912        // 27 taps * 256 ic
#define NCHUNK 216         // K chunks of 32
#define TM     128         // n tile
#define TN     128         // oc tile
#define STAGES 2
// stage layout (bytes): A_hi @0 (128*80), A_lo @10240, B_hi @20480 (128*80), B_lo @30720
#define STAGE_BYTES 40960

// ---------------- static scratch ----------------
__device__ __nv_bfloat16 g_xhi[(size_t)NB*NPTS*CIN];
__device__ __nv_bfloat16 g_xlo[(size_t)NB*NPTS*CIN];
__device__ __nv_bfloat16 g_whi[(size_t)CINNER*KTOT];   // [oc][tap*256+ic]
__device__ __nv_bfloat16 g_wlo[(size_t)CINNER*KTOT];
__device__ float    g_xp[(size_t)NB*NPTS*CINNER];      // conv output [b][n][inner]
__device__ float    g_l[(size_t)NB*HEADS*G*NPTS];      // logits -> exp in place
__device__ unsigned g_max[NB*HEADS*G];
__device__ float    g_denom_part[NB*HEADS*G*16];
__device__ float    g_denom[NB*HEADS*G];
__device__ float    g_eid_part[(size_t)32*16*G*DHD];
__device__ float    g_eid[(size_t)32*G*DHD];
__device__ float    g_proj[(size_t)NB*256*256];

// ---------------- helpers ----------------
__device__ __forceinline__ unsigned fenc(float f){
    unsigned u = __float_as_uint(f);
    return (u & 0x80000000u) ? ~u : (u | 0x80000000u);
}
__device__ __forceinline__ float fdec(unsigned u){
    u = (u & 0x80000000u) ? (u & 0x7fffffffu) : ~u;
    return __uint_as_float(u);
}
__device__ __forceinline__ uint32_t smem_u32(const void* p){
    uint32_t a;
    asm("{ .reg .u64 t; cvta.to.shared.u64 t, %1; cvt.u32.u64 %0, t; }" : "=r"(a) : "l"(p));
    return a;
}
__device__ __forceinline__ void cp16(uint32_t dst, const void* src, int srcsize){
    asm volatile("cp.async.cg.shared.global [%0], [%1], 16, %2;" :: "r"(dst), "l"(src), "r"(srcsize));
}
__device__ __forceinline__ void ldm4(unsigned* r, uint32_t addr){
    asm volatile("ldmatrix.sync.aligned.m8n8.x4.shared.b16 {%0,%1,%2,%3}, [%4];"
        : "=r"(r[0]), "=r"(r[1]), "=r"(r[2]), "=r"(r[3]) : "r"(addr));
}
__device__ __forceinline__ void mma_bf(float* c, const unsigned* a, unsigned b0, unsigned b1){
    asm volatile("mma.sync.aligned.m16n8k16.row.col.f32.bf16.bf16.f32 "
        "{%0,%1,%2,%3}, {%4,%5,%6,%7}, {%8,%9}, {%0,%1,%2,%3};"
        : "+f"(c[0]), "+f"(c[1]), "+f"(c[2]), "+f"(c[3])
        : "r"(a[0]), "r"(a[1]), "r"(a[2]), "r"(a[3]), "r"(b0), "r"(b1));
}
__device__ __forceinline__ unsigned long long pack2(float a){
    unsigned long long r; asm("mov.b64 %0, {%1, %1};" : "=l"(r) : "f"(a)); return r;
}
__device__ __forceinline__ unsigned long long pack2f(float a, float b){
    unsigned long long r; asm("mov.b64 %0, {%1, %2};" : "=l"(r) : "f"(a), "f"(b)); return r;
}
__device__ __forceinline__ void ffma2(unsigned long long& d, unsigned long long a, unsigned long long b){
    asm("fma.rn.f32x2 %0, %1, %2, %0;" : "+l"(d) : "l"(a), "l"(b));
}
__device__ __forceinline__ float2 unpack2(unsigned long long v){
    float2 r; asm("mov.b64 {%0, %1}, %2;" : "=f"(r.x), "=f"(r.y) : "l"(v)); return r;
}

// ---------------- prep: split x into bf16 hi/lo ----------------
__global__ __launch_bounds__(256) void k_split_x(const float* __restrict__ x){
    size_t i0 = ((size_t)blockIdx.x*256 + threadIdx.x)*8;
    float4 a = *(const float4*)(x + i0);
    float4 b4 = *(const float4*)(x + i0 + 4);
    float v[8] = {a.x,a.y,a.z,a.w,b4.x,b4.y,b4.z,b4.w};
    unsigned hb[8], lb[8];
    #pragma unroll
    for (int j=0;j<8;++j){
        __nv_bfloat16 h = __float2bfloat16(v[j]);
        float r = v[j] - __bfloat162float(h);
        __nv_bfloat16 l = __float2bfloat16(r);
        hb[j] = (unsigned)__bfloat16_as_ushort(h);
        lb[j] = (unsigned)__bfloat16_as_ushort(l);
    }
    uint4 ph = make_uint4(hb[0]|(hb[1]<<16), hb[2]|(hb[3]<<16), hb[4]|(hb[5]<<16), hb[6]|(hb[7]<<16));
    uint4 pl = make_uint4(lb[0]|(lb[1]<<16), lb[2]|(lb[3]<<16), lb[4]|(lb[5]<<16), lb[6]|(lb[7]<<16));
    *(uint4*)(&g_xhi[i0]) = ph;
    *(uint4*)(&g_xlo[i0]) = pl;
}

// ---------------- prep: transpose+split conv_w -> [oc][tap*256+ic] bf16 hi/lo ----------------
__global__ __launch_bounds__(256) void k_split_w(const float* __restrict__ cw){
    int oc = blockIdx.x;
    const float* src = cw + (size_t)oc*KTOT;   // [ic][27]
    for (int j=0;j<27;++j){
        int k = j*256 + threadIdx.x;           // tap=j, ic=tid
        float v = src[threadIdx.x*27 + j];
        __nv_bfloat16 h = __float2bfloat16(v);
        __nv_bfloat16 l = __float2bfloat16(v - __bfloat162float(h));
        g_whi[(size_t)oc*KTOT + k] = h;
        g_wlo[(size_t)oc*KTOT + k] = l;
    }
}

// ---------------- K init: max accumulators ----------------
__global__ void k_init_max(){
    int i = blockIdx.x*256 + threadIdx.x;
    if (i < NB*HEADS*G) g_max[i] = fenc(-3.4e38f);
}

// ---------------- K1: conv as mma.sync bf16 implicit GEMM (split both, 3 MMAs) ----------------
// CTA 128n x 128oc, 8 warps (warp tile 32x64), 2-stage pipeline, 2 CTAs/SM.
// Next-chunk cp.async issued BETWEEN MMA groups to spread LSU/crossbar pressure.
__global__ __launch_bounds__(256,2) void k1_conv_mma(const float* __restrict__ cb){
    extern __shared__ __align__(16) char sm[];
    __shared__ float s_bias[TN];
    const int tid = threadIdx.x;
    const int b = blockIdx.z, n0 = blockIdx.x*TM, oc0 = blockIdx.y*TN;
    if (tid < TN) s_bias[tid] = cb[oc0 + tid];

    const uint32_t s0 = smem_u32(sm);

    // ---- loader roles: 2 threads per row for both A (128 n-rows) and B (128 oc-rows)
    const int rowL = tid >> 1, half = tid & 1;
    const int nA = n0 + rowL;
    const int hA = nA >> 10, wA = (nA >> 5) & 31, dA = nA & 31;
    const __nv_bfloat16* xh_row = g_xhi + (size_t)b*NPTS*CIN + (size_t)nA*CIN + half*16;
    const __nv_bfloat16* xl_row = g_xlo + (size_t)b*NPTS*CIN + (size_t)nA*CIN + half*16;
    const uint32_t dstA = s0 + (uint32_t)rowL*80u + (uint32_t)half*32u;
    const __nv_bfloat16* wh_row = g_whi + (size_t)(oc0 + rowL)*KTOT + half*16;
    const __nv_bfloat16* wl_row = g_wlo + (size_t)(oc0 + rowL)*KTOT + half*16;
    const uint32_t dstB = s0 + 20480u + (uint32_t)rowL*80u + (uint32_t)half*32u;

    int cur_tap = -1;
    ptrdiff_t tap_off = 0;
    int tap_ss = 0;

    auto load_chunk = [&](int c, int buf){
        uint32_t bo = (uint32_t)buf * STAGE_BYTES;
        int tap = c >> 3;
        if (tap != cur_tap){
            cur_tap = tap;
            int dh = tap/9 - 1, dw = (tap/3)%3 - 1, dd = tap%3 - 1;
            bool valid = ((unsigned)(hA+dh) < 32u) && ((unsigned)(wA+dw) < 32u) && ((unsigned)(dA+dd) < 32u);
            tap_off = valid ? (ptrdiff_t)(dh*1024 + dw*32 + dd)*CIN : 0;
            tap_ss  = valid ? 16 : 0;
        }
        int ic0 = (c & 7) * 32;
        const __nv_bfloat16* sh = xh_row + tap_off + ic0;
        const __nv_bfloat16* sl = xl_row + tap_off + ic0;
        cp16(dstA + bo,           sh,     tap_ss);
        cp16(dstA + bo + 16,      sh + 8, tap_ss);
        cp16(dstA + bo + 10240,   sl,     tap_ss);
        cp16(dstA + bo + 10256,   sl + 8, tap_ss);
        const __nv_bfloat16* bh = wh_row + (size_t)c*32;
        const __nv_bfloat16* bl = wl_row + (size_t)c*32;
        cp16(dstB + bo,           bh,     16);
        cp16(dstB + bo + 16,      bh + 8, 16);
        cp16(dstB + bo + 10240,   bl,     16);
        cp16(dstB + bo + 10256,   bl + 8, 16);
    };

    // ---- compute role: 8 warps, wm in {0,32,64,96}, wn in {0,64}
    const int lane = tid & 31, wid = tid >> 5;
    const int wm = (wid & 3) * 32;
    const int wn = (wid >> 2) * 64;
    const uint32_t ldA = s0 + (uint32_t)(wm + (lane & 15))*80u + (uint32_t)((lane >> 4) * 16);
    const uint32_t ldB = s0 + 20480u + (uint32_t)(wn + (lane & 15))*80u + (uint32_t)((lane >> 4) * 16);

    float acc[2][8][4];
    #pragma unroll
    for (int mi=0; mi<2; ++mi)
        #pragma unroll
        for (int ni=0; ni<8; ++ni){
            acc[mi][ni][0]=0.f; acc[mi][ni][1]=0.f; acc[mi][ni][2]=0.f; acc[mi][ni][3]=0.f;
        }

    load_chunk(0, 0);
    asm volatile("cp.async.commit_group;");

    for (int c=0; c<NCHUNK; ++c){
        asm volatile("cp.async.wait_group 0;");
        __syncthreads();
        uint32_t bo = (uint32_t)(c & 1) * STAGE_BYTES;
        #pragma unroll
        for (int ks=0; ks<2; ++ks){
            uint32_t ko = (uint32_t)ks * 32u;   // 16 bf16 = 32 bytes
            unsigned ah[2][4], al[2][4], bh2[4][4], bl2[4][4];
            ldm4(ah[0], ldA + bo + ko);
            ldm4(ah[1], ldA + bo + ko + 16*80);
            #pragma unroll
            for (int nb=0; nb<4; ++nb)
                ldm4(bh2[nb], ldB + bo + ko + nb*16*80);
            ldm4(al[0], ldA + bo + ko + 10240);
            ldm4(al[1], ldA + bo + ko + 10240 + 16*80);
            #pragma unroll
            for (int nb=0; nb<4; ++nb)
                ldm4(bl2[nb], ldB + bo + ko + 10240 + nb*16*80);
            // hh block (16 MMAs)
            #pragma unroll
            for (int mi=0; mi<2; ++mi)
                #pragma unroll
                for (int nb=0; nb<4; ++nb){
                    mma_bf(acc[mi][2*nb],   ah[mi], bh2[nb][0], bh2[nb][2]);
                    mma_bf(acc[mi][2*nb+1], ah[mi], bh2[nb][1], bh2[nb][3]);
                }
            // spread the next-chunk loads into the MMA stream (once, at ks==0)
            if (ks == 0){
                if (c + 1 < NCHUNK) load_chunk(c + 1, (c + 1) & 1);
                asm volatile("cp.async.commit_group;");
            }
            // hl block
            #pragma unroll
            for (int mi=0; mi<2; ++mi)
                #pragma unroll
                for (int nb=0; nb<4; ++nb){
                    mma_bf(acc[mi][2*nb],   ah[mi], bl2[nb][0], bl2[nb][2]);
                    mma_bf(acc[mi][2*nb+1], ah[mi], bl2[nb][1], bl2[nb][3]);
                }
            // lh block
            #pragma unroll
            for (int mi=0; mi<2; ++mi)
                #pragma unroll
                for (int nb=0; nb<4; ++nb){
                    mma_bf(acc[mi][2*nb],   al[mi], bh2[nb][0], bh2[nb][2]);
                    mma_bf(acc[mi][2*nb+1], al[mi], bh2[nb][1], bh2[nb][3]);
                }
        }
    }

    // ---- epilogue: regs -> gmem with bias ----
    const int gid = lane >> 2, tig = lane & 3;
    #pragma unroll
    for (int mi=0; mi<2; ++mi){
        int row = n0 + wm + mi*16 + gid;
        float* rp = g_xp + ((size_t)b*NPTS + row)*CINNER + oc0;
        #pragma unroll
        for (int ni=0; ni<8; ++ni){
            int lc = wn + ni*8 + tig*2;
            float b0 = s_bias[lc], b1 = s_bias[lc+1];
            float2 v0 = make_float2(acc[mi][ni][0]+b0, acc[mi][ni][1]+b1);
            float2 v1 = make_float2(acc[mi][ni][2]+b0, acc[mi][ni][3]+b1);
            *(float2*)(rp + lc) = v0;
            *(float2*)(rp + lc + 8*CINNER) = v1;
        }
    }
}

// ---------------- K2: temp + scaled logits, block max -> atomicMax ----------------
__global__ __launch_bounds__(256) void k2_logits(const float* __restrict__ slw, const float* __restrict__ slb,
                                                 const float* __restrict__ adw, const float* __restrict__ adb){
    __shared__ float xs[64][68];
    __shared__ float wsm[32][72];
    __shared__ float sb[32];
    __shared__ float temps[64];
    __shared__ float mred[256];
    int tid = threadIdx.x;
    int b = blockIdx.z, h = blockIdx.y, n0 = blockIdx.x*64;
    for (int i=tid; i<2048; i+=256) wsm[i>>6][i&63] = slw[i];
    if (tid < 32) sb[tid] = slb[tid];
    const float* xpb = g_xp + ((size_t)b*NPTS + n0)*CINNER + h*DHD;
    for (int i=tid; i<1024; i+=256){
        int r = i>>4, c4 = i&15;
        *(float4*)&xs[r][c4*4] = *(const float4*)(xpb + (size_t)r*CINNER + c4*4);
    }
    __syncthreads();
    if (tid < 64){
        float s = adb[0];
        #pragma unroll 8
        for (int c=0;c<64;++c) s += xs[tid][c]*adw[c];
        s = fminf(fmaxf(s, -0.4f), 0.4f);
        temps[tid] = 1.0f/(0.5f + s);
    }
    __syncthreads();
    const float LLNE = logf(-logf(1e-6f));
    int g = tid>>3, ns = tid&7;
    float lmax = -3.4e38f;
    float* lout = g_l + ((size_t)(b*HEADS+h)*G + g)*NPTS + n0;
    #pragma unroll
    for (int i=0;i<8;++i){
        int nn = ns + i*8;
        float s = 0.f;
        #pragma unroll
        for (int c4=0;c4<16;++c4){
            float4 xv = *(const float4*)&xs[nn][c4*4];
            float4 wv = *(const float4*)&wsm[g][c4*4];
            s += xv.x*wv.x + xv.y*wv.y + xv.z*wv.z + xv.w*wv.w;
        }
        float l = (s + sb[g] - LLNE)*temps[nn];
        lout[nn] = l;
        lmax = fmaxf(lmax, l);
    }
    mred[tid] = lmax;
    __syncthreads();
    if (ns == 0){
        float m = mred[tid];
        #pragma unroll
        for (int j=1;j<8;++j) m = fmaxf(m, mred[tid+j]);
        atomicMax(&g_max[(b*HEADS+h)*G + g], fenc(m));
    }
}

// ---------------- K3: exp in place + partial denom sums ----------------
__global__ __launch_bounds__(256) void k3_exp(){
    __shared__ float red[256];
    int tid = threadIdx.x;
    int chunk = blockIdx.x, bhg = blockIdx.y;
    float m = fdec(g_max[bhg]);
    size_t base = (size_t)bhg*NPTS + (size_t)chunk*2048;
    float s = 0.f;
    #pragma unroll
    for (int i=0;i<8;++i){
        size_t idx = base + tid + i*256;
        float e = expf(g_l[idx] - m);
        g_l[idx] = e;
        s += e;
    }
    red[tid]=s; __syncthreads();
    for (int off=128; off>0; off>>=1){ if (tid<off) red[tid]+=red[tid+off]; __syncthreads(); }
    if (tid==0) g_denom_part[bhg*16 + chunk] = red[0];
}
__global__ void k3b_denom(){
    int i = blockIdx.x*256 + threadIdx.x;   // bhg
    float s = 0.f;
    #pragma unroll
    for (int c=0;c<16;++c) s += g_denom_part[i*16+c];
    g_denom[i] = s;
}

// ---------------- K5: eid partials (split-K GEMM, FFMA2 packed) ----------------
__global__ __launch_bounds__(256) void k5_eid_part(){
    __shared__ float xs[64][64];
    __shared__ float es[32][68];
    int tid = threadIdx.x;
    int chunk = blockIdx.x, bh = blockIdx.y;
    int b = bh>>3, h = bh&7;
    int g = tid>>3, cb2 = (tid&7)*8;
    unsigned long long acc2[4] = {0ULL,0ULL,0ULL,0ULL};
    for (int t=0; t<32; ++t){
        int n0 = chunk*2048 + t*64;
        __syncthreads();
        const float* xpb = g_xp + ((size_t)b*NPTS + n0)*CINNER + h*DHD;
        #pragma unroll
        for (int i=0;i<4;++i){
            int idx = tid + i*256;
            int r = idx>>4, c4 = idx&15;
            *(float4*)&xs[r][c4*4] = *(const float4*)(xpb + (size_t)r*CINNER + c4*4);
        }
        const float* lb = g_l + ((size_t)bh*G)*NPTS + n0;
        #pragma unroll
        for (int i=0;i<2;++i){
            int idx = tid + i*256;
            int r = idx>>4, c4 = idx&15;
            *(float4*)&es[r][c4*4] = *(const float4*)(lb + (size_t)r*NPTS + c4*4);
        }
        __syncthreads();
        #pragma unroll 4
        for (int n=0;n<64;++n){
            unsigned long long ev2 = pack2(es[g][n]);
            ulonglong2 x01 = *(const ulonglong2*)&xs[n][cb2];
            ulonglong2 x23 = *(const ulonglong2*)&xs[n][cb2+4];
            ffma2(acc2[0], ev2, x01.x);
            ffma2(acc2[1], ev2, x01.y);
            ffma2(acc2[2], ev2, x23.x);
            ffma2(acc2[3], ev2, x23.y);
        }
    }
    float* dst = g_eid_part + (size_t)(bh*16+chunk)*2048 + g*64 + cb2;
    #pragma unroll
    for (int j=0;j<4;++j){
        float2 p = unpack2(acc2[j]);
        dst[2*j]   = p.x;
        dst[2*j+1] = p.y;
    }
}
__global__ void k5b_eid(){
    int bh = blockIdx.x;
    int tid = threadIdx.x;
    #pragma unroll
    for (int j=0;j<8;++j){
        int s = tid + j*256;
        float acc = 0.f;
        #pragma unroll
        for (int ch=0; ch<16; ++ch) acc += g_eid_part[(size_t)(bh*16+ch)*2048 + s];
        float dn = g_denom[bh*G + (s>>6)];
        g_eid[(size_t)bh*2048 + s] = acc / (dn * (1.0f + 1e-5f));
    }
}

// ---------------- K6: proj[b][hg][o] = (eid @ out_w_slice^T) / denom ----------------
__global__ __launch_bounds__(256) void k6_proj(const float* __restrict__ ow){
    __shared__ float ev[64];
    int b = blockIdx.y, k = blockIdx.x;
    int h = k>>5, g = k&31;
    int tid = threadIdx.x;    // = o
    if (tid < 64) ev[tid] = g_eid[(size_t)(b*8+h)*2048 + g*64 + tid];
    __syncthreads();
    const float* wr = ow + (size_t)tid*CINNER + h*DHD;
    float s = 0.f;
    #pragma unroll 8
    for (int c=0;c<64;++c) s += ev[c]*wr[c];
    g_proj[((size_t)b*256 + k)*256 + tid] = s / g_denom[(b*8+h)*G + g];
}

// ---------------- K7: final = E^T(256,N) x proj(256,256) + out_b (FFMA2 packed) ----------------
__global__ __launch_bounds__(256) void k7_final(const float* __restrict__ ob, float* __restrict__ out){
    __shared__ float as2[16][132];
    __shared__ float ps[16][68];
    int tid = threadIdx.x;
    int b = blockIdx.z, n0 = blockIdx.x*128, o0 = blockIdx.y*64;
    int mf = tid&15, of = tid>>4;
    unsigned long long acc2[8][2];
    #pragma unroll
    for (int i=0;i<8;++i){ acc2[i][0]=0ULL; acc2[i][1]=0ULL; }
    for (int kt=0; kt<16; ++kt){
        int k0 = kt*16;
        __syncthreads();
        #pragma unroll
        for (int i=0;i<2;++i){
            int idx = tid + i*256;
            int r = idx>>5, c4 = idx&31;
            *(float4*)&as2[r][c4*4] = *(const float4*)(g_l + ((size_t)b*256 + k0 + r)*NPTS + n0 + c4*4);
        }
        {
            int r = tid>>4, c4 = tid&15;
            *(float4*)&ps[r][c4*4] = *(const float4*)(g_proj + ((size_t)b*256 + k0 + r)*256 + o0 + c4*4);
        }
        __syncthreads();
        #pragma unroll
        for (int kk=0;kk<16;++kk){
            float4 a0 = *(const float4*)&as2[kk][mf*8];
            float4 a1 = *(const float4*)&as2[kk][mf*8+4];
            float4 bv = *(const float4*)&ps[kk][of*4];
            unsigned long long b01 = pack2f(bv.x, bv.y);
            unsigned long long b23 = pack2f(bv.z, bv.w);
            float av[8]={a0.x,a0.y,a0.z,a0.w,a1.x,a1.y,a1.z,a1.w};
            #pragma unroll
            for (int i=0;i<8;++i){
                unsigned long long ap = pack2(av[i]);
                ffma2(acc2[i][0], ap, b01);
                ffma2(acc2[i][1], ap, b23);
            }
        }
    }
    float obv[4];
    #pragma unroll
    for (int j=0;j<4;++j) obv[j] = ob[o0 + of*4 + j];
    #pragma unroll
    for (int i=0;i<8;++i){
        int n = n0 + mf*8 + i;
        float2 p0 = unpack2(acc2[i][0]);
        float2 p1 = unpack2(acc2[i][1]);
        *(float4*)(out + ((size_t)b*NPTS + n)*256 + o0 + of*4) =
            make_float4(p0.x+obv[0], p0.y+obv[1], p1.x+obv[2], p1.y+obv[3]);
    }
}

// ---------------- launch ----------------
extern "C" void kernel_launch(void* const* d_in, const int* in_sizes, int n_in,
                              void* d_out, int out_size){
    const float* x   = (const float*)d_in[0];
    const float* cw  = (const float*)d_in[1];
    const float* cb  = (const float*)d_in[2];
    const float* slw = (const float*)d_in[3];
    const float* slb = (const float*)d_in[4];
    const float* adw = (const float*)d_in[5];
    const float* adb = (const float*)d_in[6];
    const float* ow  = (const float*)d_in[7];
    const float* ob  = (const float*)d_in[8];
    float* out = (float*)d_out;

    cudaFuncSetAttribute(k1_conv_mma, cudaFuncAttributeMaxDynamicSharedMemorySize, STAGES*STAGE_BYTES);

    k_split_x  <<<16384, 256>>>(x);
    k_split_w  <<<512, 256>>>(cw);
    k_init_max <<<4, 256>>>();
    k1_conv_mma<<<dim3(256,4,4), 256, STAGES*STAGE_BYTES>>>(cb);   // launch idx 3 -> profiled
    k2_logits  <<<dim3(512,8,4), 256>>>(slw, slb, adw, adb);
    k3_exp     <<<dim3(16,1024), 256>>>();
    k3b_denom  <<<4, 256>>>();
    k5_eid_part<<<dim3(16,32), 256>>>();
    k5b_eid    <<<32, 256>>>();
    k6_proj    <<<dim3(256,4), 256>>>(ow);
    k7_final   <<<dim3(256,4,4), 256>>>(ob, out);
}

// round 14
// speedup vs baseline: 1.1352x; 1.0439x over previous
#include <cuda_runtime.h>
#include <cuda_bf16.h>
#include <math.h>
#include <stdint.h>

#define NB     4
#define NPTS   32768
#define CIN    256
#define CINNER 512
#define HEADS  8
#define DHD    64
#define G      32
#define KTOT   6912        // 27 taps * 256 ic
#define NCHUNK 216         // K chunks of 32
#define TM     128         // n tile
#define TN     128         // oc tile
#define STAGES 2
// stage layout (bytes): A_hi @0 (128*80), A_lo @10240, B_hi @20480 (128*80), B_lo @30720
#define STAGE_BYTES 40960

// ---------------- static scratch ----------------
__device__ __nv_bfloat16 g_xhi[(size_t)NB*NPTS*CIN];
__device__ __nv_bfloat16 g_xlo[(size_t)NB*NPTS*CIN];
__device__ __nv_bfloat16 g_whi[(size_t)CINNER*KTOT];   // [oc][tap*256+ic]
__device__ __nv_bfloat16 g_wlo[(size_t)CINNER*KTOT];
__device__ float    g_xp[(size_t)NB*NPTS*CINNER];      // conv output [b][n][inner]
__device__ float    g_l[(size_t)NB*HEADS*G*NPTS];      // logits -> exp in place
__device__ unsigned g_max[NB*HEADS*G];
__device__ float    g_denom_part[NB*HEADS*G*16];
__device__ float    g_denom[NB*HEADS*G];
__device__ float    g_eid_part[(size_t)32*16*G*DHD];
__device__ float    g_eid[(size_t)32*G*DHD];
__device__ float    g_proj[(size_t)NB*256*256];

// ---------------- helpers ----------------
__device__ __forceinline__ unsigned fenc(float f){
    unsigned u = __float_as_uint(f);
    return (u & 0x80000000u) ? ~u : (u | 0x80000000u);
}
__device__ __forceinline__ float fdec(unsigned u){
    u = (u & 0x80000000u) ? (u & 0x7fffffffu) : ~u;
    return __uint_as_float(u);
}
__device__ __forceinline__ uint32_t smem_u32(const void* p){
    uint32_t a;
    asm("{ .reg .u64 t; cvta.to.shared.u64 t, %1; cvt.u32.u64 %0, t; }" : "=r"(a) : "l"(p));
    return a;
}
__device__ __forceinline__ void cp16(uint32_t dst, const void* src, int srcsize){
    asm volatile("cp.async.cg.shared.global [%0], [%1], 16, %2;" :: "r"(dst), "l"(src), "r"(srcsize));
}
__device__ __forceinline__ void ldm4(unsigned* r, uint32_t addr){
    asm volatile("ldmatrix.sync.aligned.m8n8.x4.shared.b16 {%0,%1,%2,%3}, [%4];"
        : "=r"(r[0]), "=r"(r[1]), "=r"(r[2]), "=r"(r[3]) : "r"(addr));
}
__device__ __forceinline__ void mma_bf(float* c, const unsigned* a, unsigned b0, unsigned b1){
    asm volatile("mma.sync.aligned.m16n8k16.row.col.f32.bf16.bf16.f32 "
        "{%0,%1,%2,%3}, {%4,%5,%6,%7}, {%8,%9}, {%0,%1,%2,%3};"
        : "+f"(c[0]), "+f"(c[1]), "+f"(c[2]), "+f"(c[3])
        : "r"(a[0]), "r"(a[1]), "r"(a[2]), "r"(a[3]), "r"(b0), "r"(b1));
}
__device__ __forceinline__ unsigned long long pack2(float a){
    unsigned long long r; asm("mov.b64 %0, {%1, %1};" : "=l"(r) : "f"(a)); return r;
}
__device__ __forceinline__ unsigned long long pack2f(float a, float b){
    unsigned long long r; asm("mov.b64 %0, {%1, %2};" : "=l"(r) : "f"(a), "f"(b)); return r;
}
__device__ __forceinline__ void ffma2(unsigned long long& d, unsigned long long a, unsigned long long b){
    asm("fma.rn.f32x2 %0, %1, %2, %0;" : "+l"(d) : "l"(a), "l"(b));
}
__device__ __forceinline__ float2 unpack2(unsigned long long v){
    float2 r; asm("mov.b64 {%0, %1}, %2;" : "=f"(r.x), "=f"(r.y) : "l"(v)); return r;
}

// ---------------- prep: split x into bf16 hi/lo ----------------
__global__ __launch_bounds__(256) void k_split_x(const float* __restrict__ x){
    size_t i0 = ((size_t)blockIdx.x*256 + threadIdx.x)*8;
    float4 a = *(const float4*)(x + i0);
    float4 b4 = *(const float4*)(x + i0 + 4);
    float v[8] = {a.x,a.y,a.z,a.w,b4.x,b4.y,b4.z,b4.w};
    unsigned hb[8], lb[8];
    #pragma unroll
    for (int j=0;j<8;++j){
        __nv_bfloat16 h = __float2bfloat16(v[j]);
        float r = v[j] - __bfloat162float(h);
        __nv_bfloat16 l = __float2bfloat16(r);
        hb[j] = (unsigned)__bfloat16_as_ushort(h);
        lb[j] = (unsigned)__bfloat16_as_ushort(l);
    }
    uint4 ph = make_uint4(hb[0]|(hb[1]<<16), hb[2]|(hb[3]<<16), hb[4]|(hb[5]<<16), hb[6]|(hb[7]<<16));
    uint4 pl = make_uint4(lb[0]|(lb[1]<<16), lb[2]|(lb[3]<<16), lb[4]|(lb[5]<<16), lb[6]|(lb[7]<<16));
    *(uint4*)(&g_xhi[i0]) = ph;
    *(uint4*)(&g_xlo[i0]) = pl;
}

// ---------------- prep: transpose+split conv_w -> [oc][tap*256+ic] bf16 hi/lo ----------------
__global__ __launch_bounds__(256) void k_split_w(const float* __restrict__ cw){
    int oc = blockIdx.x;
    const float* src = cw + (size_t)oc*KTOT;   // [ic][27]
    for (int j=0;j<27;++j){
        int k = j*256 + threadIdx.x;           // tap=j, ic=tid
        float v = src[threadIdx.x*27 + j];
        __nv_bfloat16 h = __float2bfloat16(v);
        __nv_bfloat16 l = __float2bfloat16(v - __bfloat162float(h));
        g_whi[(size_t)oc*KTOT + k] = h;
        g_wlo[(size_t)oc*KTOT + k] = l;
    }
}

// ---------------- K init: max accumulators ----------------
__global__ void k_init_max(){
    int i = blockIdx.x*256 + threadIdx.x;
    if (i < NB*HEADS*G) g_max[i] = fenc(-3.4e38f);
}

// ---------------- K1: conv as mma.sync bf16 implicit GEMM (split both, 3 MMAs) ----------------
// CTA 128n x 128oc, 8 warps (warp tile 32x64), 2-stage pipeline, 2 CTAs/SM.
// Next-chunk cp.async split into TWO bursts (A after hh, B after hl) inside ks==0.
__global__ __launch_bounds__(256,2) void k1_conv_mma(const float* __restrict__ cb){
    extern __shared__ __align__(16) char sm[];
    __shared__ float s_bias[TN];
    const int tid = threadIdx.x;
    const int b = blockIdx.z, n0 = blockIdx.x*TM, oc0 = blockIdx.y*TN;
    if (tid < TN) s_bias[tid] = cb[oc0 + tid];

    const uint32_t s0 = smem_u32(sm);

    // ---- loader roles: 2 threads per row for both A (128 n-rows) and B (128 oc-rows)
    const int rowL = tid >> 1, half = tid & 1;
    const int nA = n0 + rowL;
    const int hA = nA >> 10, wA = (nA >> 5) & 31, dA = nA & 31;
    const __nv_bfloat16* xh_row = g_xhi + (size_t)b*NPTS*CIN + (size_t)nA*CIN + half*16;
    const __nv_bfloat16* xl_row = g_xlo + (size_t)b*NPTS*CIN + (size_t)nA*CIN + half*16;
    const uint32_t dstA = s0 + (uint32_t)rowL*80u + (uint32_t)half*32u;
    const __nv_bfloat16* wh_row = g_whi + (size_t)(oc0 + rowL)*KTOT + half*16;
    const __nv_bfloat16* wl_row = g_wlo + (size_t)(oc0 + rowL)*KTOT + half*16;
    const uint32_t dstB = s0 + 20480u + (uint32_t)rowL*80u + (uint32_t)half*32u;

    int cur_tap = -1;
    ptrdiff_t tap_off = 0;
    int tap_ss = 0;

    auto load_A = [&](int c, int buf){
        uint32_t bo = (uint32_t)buf * STAGE_BYTES;
        int tap = c >> 3;
        if (tap != cur_tap){
            cur_tap = tap;
            int dh = tap/9 - 1, dw = (tap/3)%3 - 1, dd = tap%3 - 1;
            bool valid = ((unsigned)(hA+dh) < 32u) && ((unsigned)(wA+dw) < 32u) && ((unsigned)(dA+dd) < 32u);
            tap_off = valid ? (ptrdiff_t)(dh*1024 + dw*32 + dd)*CIN : 0;
            tap_ss  = valid ? 16 : 0;
        }
        int ic0 = (c & 7) * 32;
        const __nv_bfloat16* sh = xh_row + tap_off + ic0;
        const __nv_bfloat16* sl = xl_row + tap_off + ic0;
        cp16(dstA + bo,           sh,     tap_ss);
        cp16(dstA + bo + 16,      sh + 8, tap_ss);
        cp16(dstA + bo + 10240,   sl,     tap_ss);
        cp16(dstA + bo + 10256,   sl + 8, tap_ss);
    };
    auto load_B = [&](int c, int buf){
        uint32_t bo = (uint32_t)buf * STAGE_BYTES;
        const __nv_bfloat16* bh = wh_row + (size_t)c*32;
        const __nv_bfloat16* bl = wl_row + (size_t)c*32;
        cp16(dstB + bo,           bh,     16);
        cp16(dstB + bo + 16,      bh + 8, 16);
        cp16(dstB + bo + 10240,   bl,     16);
        cp16(dstB + bo + 10256,   bl + 8, 16);
    };

    // ---- compute role: 8 warps, wm in {0,32,64,96}, wn in {0,64}
    const int lane = tid & 31, wid = tid >> 5;
    const int wm = (wid & 3) * 32;
    const int wn = (wid >> 2) * 64;
    const uint32_t ldA = s0 + (uint32_t)(wm + (lane & 15))*80u + (uint32_t)((lane >> 4) * 16);
    const uint32_t ldB = s0 + 20480u + (uint32_t)(wn + (lane & 15))*80u + (uint32_t)((lane >> 4) * 16);

    float acc[2][8][4];
    #pragma unroll
    for (int mi=0; mi<2; ++mi)
        #pragma unroll
        for (int ni=0; ni<8; ++ni){
            acc[mi][ni][0]=0.f; acc[mi][ni][1]=0.f; acc[mi][ni][2]=0.f; acc[mi][ni][3]=0.f;
        }

    load_A(0, 0); load_B(0, 0);
    asm volatile("cp.async.commit_group;");

    for (int c=0; c<NCHUNK; ++c){
        asm volatile("cp.async.wait_group 0;");
        __syncthreads();
        uint32_t bo = (uint32_t)(c & 1) * STAGE_BYTES;
        #pragma unroll
        for (int ks=0; ks<2; ++ks){
            uint32_t ko = (uint32_t)ks * 32u;   // 16 bf16 = 32 bytes
            unsigned ah[2][4], al[2][4], bh2[4][4], bl2[4][4];
            ldm4(ah[0], ldA + bo + ko);
            ldm4(ah[1], ldA + bo + ko + 16*80);
            #pragma unroll
            for (int nb=0; nb<4; ++nb)
                ldm4(bh2[nb], ldB + bo + ko + nb*16*80);
            ldm4(al[0], ldA + bo + ko + 10240);
            ldm4(al[1], ldA + bo + ko + 10240 + 16*80);
            #pragma unroll
            for (int nb=0; nb<4; ++nb)
                ldm4(bl2[nb], ldB + bo + ko + 10240 + nb*16*80);
            // hh block (16 MMAs)
            #pragma unroll
            for (int mi=0; mi<2; ++mi)
                #pragma unroll
                for (int nb=0; nb<4; ++nb){
                    mma_bf(acc[mi][2*nb],   ah[mi], bh2[nb][0], bh2[nb][2]);
                    mma_bf(acc[mi][2*nb+1], ah[mi], bh2[nb][1], bh2[nb][3]);
                }
            if (ks == 0 && c + 1 < NCHUNK) load_A(c + 1, (c + 1) & 1);
            // hl block
            #pragma unroll
            for (int mi=0; mi<2; ++mi)
                #pragma unroll
                for (int nb=0; nb<4; ++nb){
                    mma_bf(acc[mi][2*nb],   ah[mi], bl2[nb][0], bl2[nb][2]);
                    mma_bf(acc[mi][2*nb+1], ah[mi], bl2[nb][1], bl2[nb][3]);
                }
            if (ks == 0){
                if (c + 1 < NCHUNK) load_B(c + 1, (c + 1) & 1);
                asm volatile("cp.async.commit_group;");
            }
            // lh block
            #pragma unroll
            for (int mi=0; mi<2; ++mi)
                #pragma unroll
                for (int nb=0; nb<4; ++nb){
                    mma_bf(acc[mi][2*nb],   al[mi], bh2[nb][0], bh2[nb][2]);
                    mma_bf(acc[mi][2*nb+1], al[mi], bh2[nb][1], bh2[nb][3]);
                }
        }
    }

    // ---- epilogue: regs -> gmem with bias ----
    const int gid = lane >> 2, tig = lane & 3;
    #pragma unroll
    for (int mi=0; mi<2; ++mi){
        int row = n0 + wm + mi*16 + gid;
        float* rp = g_xp + ((size_t)b*NPTS + row)*CINNER + oc0;
        #pragma unroll
        for (int ni=0; ni<8; ++ni){
            int lc = wn + ni*8 + tig*2;
            float b0 = s_bias[lc], b1 = s_bias[lc+1];
            float2 v0 = make_float2(acc[mi][ni][0]+b0, acc[mi][ni][1]+b1);
            float2 v1 = make_float2(acc[mi][ni][2]+b0, acc[mi][ni][3]+b1);
            *(float2*)(rp + lc) = v0;
            *(float2*)(rp + lc + 8*CINNER) = v1;
        }
    }
}

// ---------------- K2: temp + scaled logits (c4-outer loop: 1.8x fewer LDS) ----------------
__global__ __launch_bounds__(256) void k2_logits(const float* __restrict__ slw, const float* __restrict__ slb,
                                                 const float* __restrict__ adw, const float* __restrict__ adb){
    __shared__ float xs[64][68];
    __shared__ float wsm[32][72];
    __shared__ float sb[32];
    __shared__ float temps[64];
    __shared__ float mred[256];
    int tid = threadIdx.x;
    int b = blockIdx.z, h = blockIdx.y, n0 = blockIdx.x*64;
    for (int i=tid; i<2048; i+=256) wsm[i>>6][i&63] = slw[i];
    if (tid < 32) sb[tid] = slb[tid];
    const float* xpb = g_xp + ((size_t)b*NPTS + n0)*CINNER + h*DHD;
    for (int i=tid; i<1024; i+=256){
        int r = i>>4, c4 = i&15;
        *(float4*)&xs[r][c4*4] = *(const float4*)(xpb + (size_t)r*CINNER + c4*4);
    }
    __syncthreads();
    if (tid < 64){
        float s = adb[0];
        #pragma unroll 8
        for (int c=0;c<64;++c) s += xs[tid][c]*adw[c];
        s = fminf(fmaxf(s, -0.4f), 0.4f);
        temps[tid] = 1.0f/(0.5f + s);
    }
    __syncthreads();
    const float LLNE = logf(-logf(1e-6f));
    int g = tid>>3, ns = tid&7;
    // c4-outer: wv loaded once per c4, reused for 8 n values (same accumulation
    // order per output as before -> bitwise identical)
    float sacc[8] = {0.f,0.f,0.f,0.f,0.f,0.f,0.f,0.f};
    #pragma unroll
    for (int c4=0;c4<16;++c4){
        float4 wv = *(const float4*)&wsm[g][c4*4];
        #pragma unroll
        for (int i=0;i<8;++i){
            float4 xv = *(const float4*)&xs[ns + i*8][c4*4];
            sacc[i] += xv.x*wv.x + xv.y*wv.y + xv.z*wv.z + xv.w*wv.w;
        }
    }
    float lmax = -3.4e38f;
    float* lout = g_l + ((size_t)(b*HEADS+h)*G + g)*NPTS + n0;
    #pragma unroll
    for (int i=0;i<8;++i){
        int nn = ns + i*8;
        float l = (sacc[i] + sb[g] - LLNE)*temps[nn];
        lout[nn] = l;
        lmax = fmaxf(lmax, l);
    }
    mred[tid] = lmax;
    __syncthreads();
    if (ns == 0){
        float m = mred[tid];
        #pragma unroll
        for (int j=1;j<8;++j) m = fmaxf(m, mred[tid+j]);
        atomicMax(&g_max[(b*HEADS+h)*G + g], fenc(m));
    }
}

// ---------------- K3: exp in place + partial denom sums ----------------
__global__ __launch_bounds__(256) void k3_exp(){
    __shared__ float red[256];
    int tid = threadIdx.x;
    int chunk = blockIdx.x, bhg = blockIdx.y;
    float m = fdec(g_max[bhg]);
    size_t base = (size_t)bhg*NPTS + (size_t)chunk*2048;
    float s = 0.f;
    #pragma unroll
    for (int i=0;i<8;++i){
        size_t idx = base + tid + i*256;
        float e = expf(g_l[idx] - m);
        g_l[idx] = e;
        s += e;
    }
    red[tid]=s; __syncthreads();
    for (int off=128; off>0; off>>=1){ if (tid<off) red[tid]+=red[tid+off]; __syncthreads(); }
    if (tid==0) g_denom_part[bhg*16 + chunk] = red[0];
}
__global__ void k3b_denom(){
    int i = blockIdx.x*256 + threadIdx.x;   // bhg
    float s = 0.f;
    #pragma unroll
    for (int c=0;c<16;++c) s += g_denom_part[i*16+c];
    g_denom[i] = s;
}

// ---------------- K5: eid partials (split-K GEMM, FFMA2 packed) ----------------
__global__ __launch_bounds__(256) void k5_eid_part(){
    __shared__ float xs[64][64];
    __shared__ float es[32][68];
    int tid = threadIdx.x;
    int chunk = blockIdx.x, bh = blockIdx.y;
    int b = bh>>3, h = bh&7;
    int g = tid>>3, cb2 = (tid&7)*8;
    unsigned long long acc2[4] = {0ULL,0ULL,0ULL,0ULL};
    for (int t=0; t<32; ++t){
        int n0 = chunk*2048 + t*64;
        __syncthreads();
        const float* xpb = g_xp + ((size_t)b*NPTS + n0)*CINNER + h*DHD;
        #pragma unroll
        for (int i=0;i<4;++i){
            int idx = tid + i*256;
            int r = idx>>4, c4 = idx&15;
            *(float4*)&xs[r][c4*4] = *(const float4*)(xpb + (size_t)r*CINNER + c4*4);
        }
        const float* lb = g_l + ((size_t)bh*G)*NPTS + n0;
        #pragma unroll
        for (int i=0;i<2;++i){
            int idx = tid + i*256;
            int r = idx>>4, c4 = idx&15;
            *(float4*)&es[r][c4*4] = *(const float4*)(lb + (size_t)r*NPTS + c4*4);
        }
        __syncthreads();
        #pragma unroll 4
        for (int n=0;n<64;++n){
            unsigned long long ev2 = pack2(es[g][n]);
            ulonglong2 x01 = *(const ulonglong2*)&xs[n][cb2];
            ulonglong2 x23 = *(const ulonglong2*)&xs[n][cb2+4];
            ffma2(acc2[0], ev2, x01.x);
            ffma2(acc2[1], ev2, x01.y);
            ffma2(acc2[2], ev2, x23.x);
            ffma2(acc2[3], ev2, x23.y);
        }
    }
    float* dst = g_eid_part + (size_t)(bh*16+chunk)*2048 + g*64 + cb2;
    #pragma unroll
    for (int j=0;j<4;++j){
        float2 p = unpack2(acc2[j]);
        dst[2*j]   = p.x;
        dst[2*j+1] = p.y;
    }
}
__global__ void k5b_eid(){
    int bh = blockIdx.x;
    int tid = threadIdx.x;
    #pragma unroll
    for (int j=0;j<8;++j){
        int s = tid + j*256;
        float acc = 0.f;
        #pragma unroll
        for (int ch=0; ch<16; ++ch) acc += g_eid_part[(size_t)(bh*16+ch)*2048 + s];
        float dn = g_denom[bh*G + (s>>6)];
        g_eid[(size_t)bh*2048 + s] = acc / (dn * (1.0f + 1e-5f));
    }
}

// ---------------- K6: proj[b][hg][o] = (eid @ out_w_slice^T) / denom ----------------
__global__ __launch_bounds__(256) void k6_proj(const float* __restrict__ ow){
    __shared__ float ev[64];
    int b = blockIdx.y, k = blockIdx.x;
    int h = k>>5, g = k&31;
    int tid = threadIdx.x;    // = o
    if (tid < 64) ev[tid] = g_eid[(size_t)(b*8+h)*2048 + g*64 + tid];
    __syncthreads();
    const float* wr = ow + (size_t)tid*CINNER + h*DHD;
    float s = 0.f;
    #pragma unroll 8
    for (int c=0;c<64;++c) s += ev[c]*wr[c];
    g_proj[((size_t)b*256 + k)*256 + tid] = s / g_denom[(b*8+h)*G + g];
}

// ---------------- K7: final = E^T(256,N) x proj(256,256) + out_b (FFMA2 packed) ----------------
__global__ __launch_bounds__(256) void k7_final(const float* __restrict__ ob, float* __restrict__ out){
    __shared__ float as2[16][132];
    __shared__ float ps[16][68];
    int tid = threadIdx.x;
    int b = blockIdx.z, n0 = blockIdx.x*128, o0 = blockIdx.y*64;
    int mf = tid&15, of = tid>>4;
    unsigned long long acc2[8][2];
    #pragma unroll
    for (int i=0;i<8;++i){ acc2[i][0]=0ULL; acc2[i][1]=0ULL; }
    for (int kt=0; kt<16; ++kt){
        int k0 = kt*16;
        __syncthreads();
        #pragma unroll
        for (int i=0;i<2;++i){
            int idx = tid + i*256;
            int r = idx>>5, c4 = idx&31;
            *(float4*)&as2[r][c4*4] = *(const float4*)(g_l + ((size_t)b*256 + k0 + r)*NPTS + n0 + c4*4);
        }
        {
            int r = tid>>4, c4 = tid&15;
            *(float4*)&ps[r][c4*4] = *(const float4*)(g_proj + ((size_t)b*256 + k0 + r)*256 + o0 + c4*4);
        }
        __syncthreads();
        #pragma unroll
        for (int kk=0;kk<16;++kk){
            float4 a0 = *(const float4*)&as2[kk][mf*8];
            float4 a1 = *(const float4*)&as2[kk][mf*8+4];
            float4 bv = *(const float4*)&ps[kk][of*4];
            unsigned long long b01 = pack2f(bv.x, bv.y);
            unsigned long long b23 = pack2f(bv.z, bv.w);
            float av[8]={a0.x,a0.y,a0.z,a0.w,a1.x,a1.y,a1.z,a1.w};
            #pragma unroll
            for (int i=0;i<8;++i){
                unsigned long long ap = pack2(av[i]);
                ffma2(acc2[i][0], ap, b01);
                ffma2(acc2[i][1], ap, b23);
            }
        }
    }
    float obv[4];
    #pragma unroll
    for (int j=0;j<4;++j) obv[j] = ob[o0 + of*4 + j];
    #pragma unroll
    for (int i=0;i<8;++i){
        int n = n0 + mf*8 + i;
        float2 p0 = unpack2(acc2[i][0]);
        float2 p1 = unpack2(acc2[i][1]);
        *(float4*)(out + ((size_t)b*NPTS + n)*256 + o0 + of*4) =
            make_float4(p0.x+obv[0], p0.y+obv[1], p1.x+obv[2], p1.y+obv[3]);
    }
}

// ---------------- launch ----------------
extern "C" void kernel_launch(void* const* d_in, const int* in_sizes, int n_in,
                              void* d_out, int out_size){
    const float* x   = (const float*)d_in[0];
    const float* cw  = (const float*)d_in[1];
    const float* cb  = (const float*)d_in[2];
    const float* slw = (const float*)d_in[3];
    const float* slb = (const float*)d_in[4];
    const float* adw = (const float*)d_in[5];
    const float* adb = (const float*)d_in[6];
    const float* ow  = (const float*)d_in[7];
    const float* ob  = (const float*)d_in[8];
    float* out = (float*)d_out;

    cudaFuncSetAttribute(k1_conv_mma, cudaFuncAttributeMaxDynamicSharedMemorySize, STAGES*STAGE_BYTES);

    k_split_x  <<<16384, 256>>>(x);
    k_split_w  <<<512, 256>>>(cw);
    k_init_max <<<4, 256>>>();
    k1_conv_mma<<<dim3(256,4,4), 256, STAGES*STAGE_BYTES>>>(cb);   // launch idx 3 -> profiled
    k2_logits  <<<dim3(512,8,4), 256>>>(slw, slb, adw, adb);
    k3_exp     <<<dim3(16,1024), 256>>>();
    k3b_denom  <<<4, 256>>>();
    k5_eid_part<<<dim3(16,32), 256>>>();
    k5b_eid    <<<32, 256>>>();
    k6_proj    <<<dim3(256,4), 256>>>(ow);
    k7_final   <<<dim3(256,4,4), 256>>>(ob, out);
}

// round 15
// speedup vs baseline: 1.2177x; 1.0727x over previous
#include <cuda_runtime.h>
#include <cuda_bf16.h>
#include <math.h>
#include <stdint.h>

#define NB     4
#define NPTS   32768
#define CIN    256
#define CINNER 512
#define HEADS  8
#define DHD    64
#define G      32
#define KTOT   6912        // 27 taps * 256 ic
#define NCHUNK 216         // K chunks of 32
#define TM     128         // n tile
#define TN     128         // oc tile
#define STAGES 2
// stage layout (bytes): A_hi @0 (128*80), A_lo @10240, B_hi @20480 (128*80), B_lo @30720
#define STAGE_BYTES 40960

// ---------------- static scratch ----------------
__device__ __nv_bfloat16 g_xhi[(size_t)NB*NPTS*CIN];
__device__ __nv_bfloat16 g_xlo[(size_t)NB*NPTS*CIN];
__device__ __nv_bfloat16 g_whi[(size_t)CINNER*KTOT];   // [oc][tap*256+ic]
__device__ __nv_bfloat16 g_wlo[(size_t)CINNER*KTOT];
__device__ float    g_xp[(size_t)NB*NPTS*CINNER];      // conv output [b][n][inner]
__device__ float    g_l[(size_t)NB*HEADS*G*NPTS];      // logits -> exp in place
__device__ unsigned g_max[NB*HEADS*G];
__device__ float    g_denom_part[NB*HEADS*G*16];
__device__ float    g_denom[NB*HEADS*G];
__device__ float    g_eid_part[(size_t)32*16*G*DHD];
__device__ float    g_eid[(size_t)32*G*DHD];
__device__ float    g_proj[(size_t)NB*256*256];

// ---------------- helpers ----------------
__device__ __forceinline__ unsigned fenc(float f){
    unsigned u = __float_as_uint(f);
    return (u & 0x80000000u) ? ~u : (u | 0x80000000u);
}
__device__ __forceinline__ float fdec(unsigned u){
    u = (u & 0x80000000u) ? (u & 0x7fffffffu) : ~u;
    return __uint_as_float(u);
}
__device__ __forceinline__ uint32_t smem_u32(const void* p){
    uint32_t a;
    asm("{ .reg .u64 t; cvta.to.shared.u64 t, %1; cvt.u32.u64 %0, t; }" : "=r"(a) : "l"(p));
    return a;
}
__device__ __forceinline__ void cp16(uint32_t dst, const void* src, int srcsize){
    asm volatile("cp.async.cg.shared.global [%0], [%1], 16, %2;" :: "r"(dst), "l"(src), "r"(srcsize));
}
__device__ __forceinline__ void ldm4(unsigned* r, uint32_t addr){
    asm volatile("ldmatrix.sync.aligned.m8n8.x4.shared.b16 {%0,%1,%2,%3}, [%4];"
        : "=r"(r[0]), "=r"(r[1]), "=r"(r[2]), "=r"(r[3]) : "r"(addr));
}
__device__ __forceinline__ void mma_bf(float* c, const unsigned* a, unsigned b0, unsigned b1){
    asm volatile("mma.sync.aligned.m16n8k16.row.col.f32.bf16.bf16.f32 "
        "{%0,%1,%2,%3}, {%4,%5,%6,%7}, {%8,%9}, {%0,%1,%2,%3};"
        : "+f"(c[0]), "+f"(c[1]), "+f"(c[2]), "+f"(c[3])
        : "r"(a[0]), "r"(a[1]), "r"(a[2]), "r"(a[3]), "r"(b0), "r"(b1));
}
__device__ __forceinline__ unsigned long long pack2(float a){
    unsigned long long r; asm("mov.b64 %0, {%1, %1};" : "=l"(r) : "f"(a)); return r;
}
__device__ __forceinline__ unsigned long long pack2f(float a, float b){
    unsigned long long r; asm("mov.b64 %0, {%1, %2};" : "=l"(r) : "f"(a), "f"(b)); return r;
}
__device__ __forceinline__ void ffma2(unsigned long long& d, unsigned long long a, unsigned long long b){
    asm("fma.rn.f32x2 %0, %1, %2, %0;" : "+l"(d) : "l"(a), "l"(b));
}
__device__ __forceinline__ float2 unpack2(unsigned long long v){
    float2 r; asm("mov.b64 {%0, %1}, %2;" : "=f"(r.x), "=f"(r.y) : "l"(v)); return r;
}

// ---------------- prep: split x into bf16 hi/lo ----------------
__global__ __launch_bounds__(256) void k_split_x(const float* __restrict__ x){
    size_t i0 = ((size_t)blockIdx.x*256 + threadIdx.x)*8;
    float4 a = *(const float4*)(x + i0);
    float4 b4 = *(const float4*)(x + i0 + 4);
    float v[8] = {a.x,a.y,a.z,a.w,b4.x,b4.y,b4.z,b4.w};
    unsigned hb[8], lb[8];
    #pragma unroll
    for (int j=0;j<8;++j){
        __nv_bfloat16 h = __float2bfloat16(v[j]);
        float r = v[j] - __bfloat162float(h);
        __nv_bfloat16 l = __float2bfloat16(r);
        hb[j] = (unsigned)__bfloat16_as_ushort(h);
        lb[j] = (unsigned)__bfloat16_as_ushort(l);
    }
    uint4 ph = make_uint4(hb[0]|(hb[1]<<16), hb[2]|(hb[3]<<16), hb[4]|(hb[5]<<16), hb[6]|(hb[7]<<16));
    uint4 pl = make_uint4(lb[0]|(lb[1]<<16), lb[2]|(lb[3]<<16), lb[4]|(lb[5]<<16), lb[6]|(lb[7]<<16));
    *(uint4*)(&g_xhi[i0]) = ph;
    *(uint4*)(&g_xlo[i0]) = pl;
}

// ---------------- prep: transpose+split conv_w -> [oc][tap*256+ic] bf16 hi/lo ----------------
__global__ __launch_bounds__(256) void k_split_w(const float* __restrict__ cw){
    int oc = blockIdx.x;
    const float* src = cw + (size_t)oc*KTOT;   // [ic][27]
    for (int j=0;j<27;++j){
        int k = j*256 + threadIdx.x;           // tap=j, ic=tid
        float v = src[threadIdx.x*27 + j];
        __nv_bfloat16 h = __float2bfloat16(v);
        __nv_bfloat16 l = __float2bfloat16(v - __bfloat162float(h));
        g_whi[(size_t)oc*KTOT + k] = h;
        g_wlo[(size_t)oc*KTOT + k] = l;
    }
}

// ---------------- K init: max accumulators ----------------
__global__ void k_init_max(){
    int i = blockIdx.x*256 + threadIdx.x;
    if (i < NB*HEADS*G) g_max[i] = fenc(-3.4e38f);
}

// ---------------- K1: conv as mma.sync bf16 implicit GEMM (split both, 3 MMAs) ----------------
// CTA 128n x 128oc, 8 warps (warp tile 32x64), 2-stage pipeline, 2 CTAs/SM.
// Finest load spread: only hi ldmatrix before MMAs; lo ldmatrix after hh block;
// prefetch A after hh(ks0), prefetch B after hh(ks1), commit at ks1.
__global__ __launch_bounds__(256,2) void k1_conv_mma(const float* __restrict__ cb){
    extern __shared__ __align__(16) char sm[];
    __shared__ float s_bias[TN];
    const int tid = threadIdx.x;
    const int b = blockIdx.z, n0 = blockIdx.x*TM, oc0 = blockIdx.y*TN;
    if (tid < TN) s_bias[tid] = cb[oc0 + tid];

    const uint32_t s0 = smem_u32(sm);

    // ---- loader roles: 2 threads per row for both A (128 n-rows) and B (128 oc-rows)
    const int rowL = tid >> 1, half = tid & 1;
    const int nA = n0 + rowL;
    const int hA = nA >> 10, wA = (nA >> 5) & 31, dA = nA & 31;
    const __nv_bfloat16* xh_row = g_xhi + (size_t)b*NPTS*CIN + (size_t)nA*CIN + half*16;
    const __nv_bfloat16* xl_row = g_xlo + (size_t)b*NPTS*CIN + (size_t)nA*CIN + half*16;
    const uint32_t dstA = s0 + (uint32_t)rowL*80u + (uint32_t)half*32u;
    const __nv_bfloat16* wh_row = g_whi + (size_t)(oc0 + rowL)*KTOT + half*16;
    const __nv_bfloat16* wl_row = g_wlo + (size_t)(oc0 + rowL)*KTOT + half*16;
    const uint32_t dstB = s0 + 20480u + (uint32_t)rowL*80u + (uint32_t)half*32u;

    int cur_tap = -1;
    ptrdiff_t tap_off = 0;
    int tap_ss = 0;

    auto load_A = [&](int c, int buf){
        uint32_t bo = (uint32_t)buf * STAGE_BYTES;
        int tap = c >> 3;
        if (tap != cur_tap){
            cur_tap = tap;
            int dh = tap/9 - 1, dw = (tap/3)%3 - 1, dd = tap%3 - 1;
            bool valid = ((unsigned)(hA+dh) < 32u) && ((unsigned)(wA+dw) < 32u) && ((unsigned)(dA+dd) < 32u);
            tap_off = valid ? (ptrdiff_t)(dh*1024 + dw*32 + dd)*CIN : 0;
            tap_ss  = valid ? 16 : 0;
        }
        int ic0 = (c & 7) * 32;
        const __nv_bfloat16* sh = xh_row + tap_off + ic0;
        const __nv_bfloat16* sl = xl_row + tap_off + ic0;
        cp16(dstA + bo,           sh,     tap_ss);
        cp16(dstA + bo + 16,      sh + 8, tap_ss);
        cp16(dstA + bo + 10240,   sl,     tap_ss);
        cp16(dstA + bo + 10256,   sl + 8, tap_ss);
    };
    auto load_B = [&](int c, int buf){
        uint32_t bo = (uint32_t)buf * STAGE_BYTES;
        const __nv_bfloat16* bh = wh_row + (size_t)c*32;
        const __nv_bfloat16* bl = wl_row + (size_t)c*32;
        cp16(dstB + bo,           bh,     16);
        cp16(dstB + bo + 16,      bh + 8, 16);
        cp16(dstB + bo + 10240,   bl,     16);
        cp16(dstB + bo + 10256,   bl + 8, 16);
    };

    // ---- compute role: 8 warps, wm in {0,32,64,96}, wn in {0,64}
    const int lane = tid & 31, wid = tid >> 5;
    const int wm = (wid & 3) * 32;
    const int wn = (wid >> 2) * 64;
    const uint32_t ldA = s0 + (uint32_t)(wm + (lane & 15))*80u + (uint32_t)((lane >> 4) * 16);
    const uint32_t ldB = s0 + 20480u + (uint32_t)(wn + (lane & 15))*80u + (uint32_t)((lane >> 4) * 16);

    float acc[2][8][4];
    #pragma unroll
    for (int mi=0; mi<2; ++mi)
        #pragma unroll
        for (int ni=0; ni<8; ++ni){
            acc[mi][ni][0]=0.f; acc[mi][ni][1]=0.f; acc[mi][ni][2]=0.f; acc[mi][ni][3]=0.f;
        }

    load_A(0, 0); load_B(0, 0);
    asm volatile("cp.async.commit_group;");

    for (int c=0; c<NCHUNK; ++c){
        asm volatile("cp.async.wait_group 0;");
        __syncthreads();
        uint32_t bo = (uint32_t)(c & 1) * STAGE_BYTES;
        #pragma unroll
        for (int ks=0; ks<2; ++ks){
            uint32_t ko = (uint32_t)ks * 32u;   // 16 bf16 = 32 bytes
            unsigned ah[2][4], al[2][4], bh2[4][4], bl2[4][4];
            // hi fragments only before the first MMA block
            ldm4(ah[0], ldA + bo + ko);
            ldm4(ah[1], ldA + bo + ko + 16*80);
            #pragma unroll
            for (int nb=0; nb<4; ++nb)
                ldm4(bh2[nb], ldB + bo + ko + nb*16*80);
            // hh block (16 MMAs)
            #pragma unroll
            for (int mi=0; mi<2; ++mi)
                #pragma unroll
                for (int nb=0; nb<4; ++nb){
                    mma_bf(acc[mi][2*nb],   ah[mi], bh2[nb][0], bh2[nb][2]);
                    mma_bf(acc[mi][2*nb+1], ah[mi], bh2[nb][1], bh2[nb][3]);
                }
            // prefetch + lo fragments issued under cover of the hh MMAs
            if (ks == 0){
                if (c + 1 < NCHUNK) load_A(c + 1, (c + 1) & 1);
            } else {
                if (c + 1 < NCHUNK) load_B(c + 1, (c + 1) & 1);
                asm volatile("cp.async.commit_group;");
            }
            ldm4(al[0], ldA + bo + ko + 10240);
            ldm4(al[1], ldA + bo + ko + 10240 + 16*80);
            #pragma unroll
            for (int nb=0; nb<4; ++nb)
                ldm4(bl2[nb], ldB + bo + ko + 10240 + nb*16*80);
            // hl block
            #pragma unroll
            for (int mi=0; mi<2; ++mi)
                #pragma unroll
                for (int nb=0; nb<4; ++nb){
                    mma_bf(acc[mi][2*nb],   ah[mi], bl2[nb][0], bl2[nb][2]);
                    mma_bf(acc[mi][2*nb+1], ah[mi], bl2[nb][1], bl2[nb][3]);
                }
            // lh block
            #pragma unroll
            for (int mi=0; mi<2; ++mi)
                #pragma unroll
                for (int nb=0; nb<4; ++nb){
                    mma_bf(acc[mi][2*nb],   al[mi], bh2[nb][0], bh2[nb][2]);
                    mma_bf(acc[mi][2*nb+1], al[mi], bh2[nb][1], bh2[nb][3]);
                }
        }
    }

    // ---- epilogue: regs -> gmem with bias ----
    const int gid = lane >> 2, tig = lane & 3;
    #pragma unroll
    for (int mi=0; mi<2; ++mi){
        int row = n0 + wm + mi*16 + gid;
        float* rp = g_xp + ((size_t)b*NPTS + row)*CINNER + oc0;
        #pragma unroll
        for (int ni=0; ni<8; ++ni){
            int lc = wn + ni*8 + tig*2;
            float b0 = s_bias[lc], b1 = s_bias[lc+1];
            float2 v0 = make_float2(acc[mi][ni][0]+b0, acc[mi][ni][1]+b1);
            float2 v1 = make_float2(acc[mi][ni][2]+b0, acc[mi][ni][3]+b1);
            *(float2*)(rp + lc) = v0;
            *(float2*)(rp + lc + 8*CINNER) = v1;
        }
    }
}

// ---------------- K2: temp + scaled logits (c4-outer loop) ----------------
__global__ __launch_bounds__(256) void k2_logits(const float* __restrict__ slw, const float* __restrict__ slb,
                                                 const float* __restrict__ adw, const float* __restrict__ adb){
    __shared__ float xs[64][68];
    __shared__ float wsm[32][72];
    __shared__ float sb[32];
    __shared__ float temps[64];
    __shared__ float mred[256];
    int tid = threadIdx.x;
    int b = blockIdx.z, h = blockIdx.y, n0 = blockIdx.x*64;
    for (int i=tid; i<2048; i+=256) wsm[i>>6][i&63] = slw[i];
    if (tid < 32) sb[tid] = slb[tid];
    const float* xpb = g_xp + ((size_t)b*NPTS + n0)*CINNER + h*DHD;
    for (int i=tid; i<1024; i+=256){
        int r = i>>4, c4 = i&15;
        *(float4*)&xs[r][c4*4] = *(const float4*)(xpb + (size_t)r*CINNER + c4*4);
    }
    __syncthreads();
    if (tid < 64){
        float s = adb[0];
        #pragma unroll 8
        for (int c=0;c<64;++c) s += xs[tid][c]*adw[c];
        s = fminf(fmaxf(s, -0.4f), 0.4f);
        temps[tid] = 1.0f/(0.5f + s);
    }
    __syncthreads();
    const float LLNE = logf(-logf(1e-6f));
    int g = tid>>3, ns = tid&7;
    float sacc[8] = {0.f,0.f,0.f,0.f,0.f,0.f,0.f,0.f};
    #pragma unroll
    for (int c4=0;c4<16;++c4){
        float4 wv = *(const float4*)&wsm[g][c4*4];
        #pragma unroll
        for (int i=0;i<8;++i){
            float4 xv = *(const float4*)&xs[ns + i*8][c4*4];
            sacc[i] += xv.x*wv.x + xv.y*wv.y + xv.z*wv.z + xv.w*wv.w;
        }
    }
    float lmax = -3.4e38f;
    float* lout = g_l + ((size_t)(b*HEADS+h)*G + g)*NPTS + n0;
    #pragma unroll
    for (int i=0;i<8;++i){
        int nn = ns + i*8;
        float l = (sacc[i] + sb[g] - LLNE)*temps[nn];
        lout[nn] = l;
        lmax = fmaxf(lmax, l);
    }
    mred[tid] = lmax;
    __syncthreads();
    if (ns == 0){
        float m = mred[tid];
        #pragma unroll
        for (int j=1;j<8;++j) m = fmaxf(m, mred[tid+j]);
        atomicMax(&g_max[(b*HEADS+h)*G + g], fenc(m));
    }
}

// ---------------- K3: exp in place + partial denom sums ----------------
__global__ __launch_bounds__(256) void k3_exp(){
    __shared__ float red[256];
    int tid = threadIdx.x;
    int chunk = blockIdx.x, bhg = blockIdx.y;
    float m = fdec(g_max[bhg]);
    size_t base = (size_t)bhg*NPTS + (size_t)chunk*2048;
    float s = 0.f;
    #pragma unroll
    for (int i=0;i<8;++i){
        size_t idx = base + tid + i*256;
        float e = expf(g_l[idx] - m);
        g_l[idx] = e;
        s += e;
    }
    red[tid]=s; __syncthreads();
    for (int off=128; off>0; off>>=1){ if (tid<off) red[tid]+=red[tid+off]; __syncthreads(); }
    if (tid==0) g_denom_part[bhg*16 + chunk] = red[0];
}
__global__ void k3b_denom(){
    int i = blockIdx.x*256 + threadIdx.x;   // bhg
    float s = 0.f;
    #pragma unroll
    for (int c=0;c<16;++c) s += g_denom_part[i*16+c];
    g_denom[i] = s;
}

// ---------------- K5: eid partials (split-K GEMM, FFMA2 packed) ----------------
__global__ __launch_bounds__(256) void k5_eid_part(){
    __shared__ float xs[64][64];
    __shared__ float es[32][68];
    int tid = threadIdx.x;
    int chunk = blockIdx.x, bh = blockIdx.y;
    int b = bh>>3, h = bh&7;
    int g = tid>>3, cb2 = (tid&7)*8;
    unsigned long long acc2[4] = {0ULL,0ULL,0ULL,0ULL};
    for (int t=0; t<32; ++t){
        int n0 = chunk*2048 + t*64;
        __syncthreads();
        const float* xpb = g_xp + ((size_t)b*NPTS + n0)*CINNER + h*DHD;
        #pragma unroll
        for (int i=0;i<4;++i){
            int idx = tid + i*256;
            int r = idx>>4, c4 = idx&15;
            *(float4*)&xs[r][c4*4] = *(const float4*)(xpb + (size_t)r*CINNER + c4*4);
        }
        const float* lb = g_l + ((size_t)bh*G)*NPTS + n0;
        #pragma unroll
        for (int i=0;i<2;++i){
            int idx = tid + i*256;
            int r = idx>>4, c4 = idx&15;
            *(float4*)&es[r][c4*4] = *(const float4*)(lb + (size_t)r*NPTS + c4*4);
        }
        __syncthreads();
        #pragma unroll 4
        for (int n=0;n<64;++n){
            unsigned long long ev2 = pack2(es[g][n]);
            ulonglong2 x01 = *(const ulonglong2*)&xs[n][cb2];
            ulonglong2 x23 = *(const ulonglong2*)&xs[n][cb2+4];
            ffma2(acc2[0], ev2, x01.x);
            ffma2(acc2[1], ev2, x01.y);
            ffma2(acc2[2], ev2, x23.x);
            ffma2(acc2[3], ev2, x23.y);
        }
    }
    float* dst = g_eid_part + (size_t)(bh*16+chunk)*2048 + g*64 + cb2;
    #pragma unroll
    for (int j=0;j<4;++j){
        float2 p = unpack2(acc2[j]);
        dst[2*j]   = p.x;
        dst[2*j+1] = p.y;
    }
}
__global__ void k5b_eid(){
    int bh = blockIdx.x;
    int tid = threadIdx.x;
    #pragma unroll
    for (int j=0;j<8;++j){
        int s = tid + j*256;
        float acc = 0.f;
        #pragma unroll
        for (int ch=0; ch<16; ++ch) acc += g_eid_part[(size_t)(bh*16+ch)*2048 + s];
        float dn = g_denom[bh*G + (s>>6)];
        g_eid[(size_t)bh*2048 + s] = acc / (dn * (1.0f + 1e-5f));
    }
}

// ---------------- K6: proj[b][hg][o] = (eid @ out_w_slice^T) / denom ----------------
__global__ __launch_bounds__(256) void k6_proj(const float* __restrict__ ow){
    __shared__ float ev[64];
    int b = blockIdx.y, k = blockIdx.x;
    int h = k>>5, g = k&31;
    int tid = threadIdx.x;    // = o
    if (tid < 64) ev[tid] = g_eid[(size_t)(b*8+h)*2048 + g*64 + tid];
    __syncthreads();
    const float* wr = ow + (size_t)tid*CINNER + h*DHD;
    float s = 0.f;
    #pragma unroll 8
    for (int c=0;c<64;++c) s += ev[c]*wr[c];
    g_proj[((size_t)b*256 + k)*256 + tid] = s / g_denom[(b*8+h)*G + g];
}

// ---------------- K7: final = E^T(256,N) x proj(256,256) + out_b (FFMA2 packed) ----------------
__global__ __launch_bounds__(256) void k7_final(const float* __restrict__ ob, float* __restrict__ out){
    __shared__ float as2[16][132];
    __shared__ float ps[16][68];
    int tid = threadIdx.x;
    int b = blockIdx.z, n0 = blockIdx.x*128, o0 = blockIdx.y*64;
    int mf = tid&15, of = tid>>4;
    unsigned long long acc2[8][2];
    #pragma unroll
    for (int i=0;i<8;++i){ acc2[i][0]=0ULL; acc2[i][1]=0ULL; }
    for (int kt=0; kt<16; ++kt){
        int k0 = kt*16;
        __syncthreads();
        #pragma unroll
        for (int i=0;i<2;++i){
            int idx = tid + i*256;
            int r = idx>>5, c4 = idx&31;
            *(float4*)&as2[r][c4*4] = *(const float4*)(g_l + ((size_t)b*256 + k0 + r)*NPTS + n0 + c4*4);
        }
        {
            int r = tid>>4, c4 = tid&15;
            *(float4*)&ps[r][c4*4] = *(const float4*)(g_proj + ((size_t)b*256 + k0 + r)*256 + o0 + c4*4);
        }
        __syncthreads();
        #pragma unroll
        for (int kk=0;kk<16;++kk){
            float4 a0 = *(const float4*)&as2[kk][mf*8];
            float4 a1 = *(const float4*)&as2[kk][mf*8+4];
            float4 bv = *(const float4*)&ps[kk][of*4];
            unsigned long long b01 = pack2f(bv.x, bv.y);
            unsigned long long b23 = pack2f(bv.z, bv.w);
            float av[8]={a0.x,a0.y,a0.z,a0.w,a1.x,a1.y,a1.z,a1.w};
            #pragma unroll
            for (int i=0;i<8;++i){
                unsigned long long ap = pack2(av[i]);
                ffma2(acc2[i][0], ap, b01);
                ffma2(acc2[i][1], ap, b23);
            }
        }
    }
    float obv[4];
    #pragma unroll
    for (int j=0;j<4;++j) obv[j] = ob[o0 + of*4 + j];
    #pragma unroll
    for (int i=0;i<8;++i){
        int n = n0 + mf*8 + i;
        float2 p0 = unpack2(acc2[i][0]);
        float2 p1 = unpack2(acc2[i][1]);
        *(float4*)(out + ((size_t)b*NPTS + n)*256 + o0 + of*4) =
            make_float4(p0.x+obv[0], p0.y+obv[1], p1.x+obv[2], p1.y+obv[3]);
    }
}

// ---------------- launch ----------------
extern "C" void kernel_launch(void* const* d_in, const int* in_sizes, int n_in,
                              void* d_out, int out_size){
    const float* x   = (const float*)d_in[0];
    const float* cw  = (const float*)d_in[1];
    const float* cb  = (const float*)d_in[2];
    const float* slw = (const float*)d_in[3];
    const float* slb = (const float*)d_in[4];
    const float* adw = (const float*)d_in[5];
    const float* adb = (const float*)d_in[6];
    const float* ow  = (const float*)d_in[7];
    const float* ob  = (const float*)d_in[8];
    float* out = (float*)d_out;

    cudaFuncSetAttribute(k1_conv_mma, cudaFuncAttributeMaxDynamicSharedMemorySize, STAGES*STAGE_BYTES);

    k_split_x  <<<16384, 256>>>(x);
    k_split_w  <<<512, 256>>>(cw);
    k_init_max <<<4, 256>>>();
    k1_conv_mma<<<dim3(256,4,4), 256, STAGES*STAGE_BYTES>>>(cb);   // launch idx 3 -> profiled
    k2_logits  <<<dim3(512,8,4), 256>>>(slw, slb, adw, adb);
    k3_exp     <<<dim3(16,1024), 256>>>();
    k3b_denom  <<<4, 256>>>();
    k5_eid_part<<<dim3(16,32), 256>>>();
    k5b_eid    <<<32, 256>>>();
    k6_proj    <<<dim3(256,4), 256>>>(ow);
    k7_final   <<<dim3(256,4,4), 256>>>(ob, out);
}

// round 16
// speedup vs baseline: 1.2419x; 1.0199x over previous
#include <cuda_runtime.h>
#include <cuda_bf16.h>
#include <math.h>
#include <stdint.h>

#define NB     4
#define NPTS   32768
#define CIN    256
#define CINNER 512
#define HEADS  8
#define DHD    64
#define G      32
#define KTOT   6912        // 27 taps * 256 ic
#define NCHUNK 216         // K chunks of 32
#define TM     128         // n tile
#define TN     128         // oc tile
#define STAGES 2
// stage layout (bytes): A_hi @0 (128*80), A_lo @10240, B_hi @20480 (128*80), B_lo @30720
#define STAGE_BYTES 40960

// ---------------- static scratch ----------------
__device__ __nv_bfloat16 g_xhi[(size_t)NB*NPTS*CIN];
__device__ __nv_bfloat16 g_xlo[(size_t)NB*NPTS*CIN];
__device__ __nv_bfloat16 g_whi[(size_t)CINNER*KTOT];   // [oc][tap*256+ic]
__device__ __nv_bfloat16 g_wlo[(size_t)CINNER*KTOT];
__device__ float    g_xp[(size_t)NB*NPTS*CINNER];      // conv output [b][n][inner]
__device__ float    g_l[(size_t)NB*HEADS*G*NPTS];      // logits -> exp in place
__device__ unsigned g_max[NB*HEADS*G];
__device__ float    g_denom_part[NB*HEADS*G*16];
__device__ float    g_denom[NB*HEADS*G];
__device__ float    g_eid_part[(size_t)32*16*G*DHD];
__device__ float    g_eid[(size_t)32*G*DHD];
__device__ float    g_proj[(size_t)NB*256*256];

// ---------------- helpers ----------------
__device__ __forceinline__ unsigned fenc(float f){
    unsigned u = __float_as_uint(f);
    return (u & 0x80000000u) ? ~u : (u | 0x80000000u);
}
__device__ __forceinline__ float fdec(unsigned u){
    u = (u & 0x80000000u) ? (u & 0x7fffffffu) : ~u;
    return __uint_as_float(u);
}
__device__ __forceinline__ uint32_t smem_u32(const void* p){
    uint32_t a;
    asm("{ .reg .u64 t; cvta.to.shared.u64 t, %1; cvt.u32.u64 %0, t; }" : "=r"(a) : "l"(p));
    return a;
}
__device__ __forceinline__ void cp16(uint32_t dst, const void* src, int srcsize){
    asm volatile("cp.async.cg.shared.global [%0], [%1], 16, %2;" :: "r"(dst), "l"(src), "r"(srcsize));
}
__device__ __forceinline__ void ldm4(unsigned* r, uint32_t addr){
    asm volatile("ldmatrix.sync.aligned.m8n8.x4.shared.b16 {%0,%1,%2,%3}, [%4];"
        : "=r"(r[0]), "=r"(r[1]), "=r"(r[2]), "=r"(r[3]) : "r"(addr));
}
__device__ __forceinline__ void mma_bf(float* c, const unsigned* a, unsigned b0, unsigned b1){
    asm volatile("mma.sync.aligned.m16n8k16.row.col.f32.bf16.bf16.f32 "
        "{%0,%1,%2,%3}, {%4,%5,%6,%7}, {%8,%9}, {%0,%1,%2,%3};"
        : "+f"(c[0]), "+f"(c[1]), "+f"(c[2]), "+f"(c[3])
        : "r"(a[0]), "r"(a[1]), "r"(a[2]), "r"(a[3]), "r"(b0), "r"(b1));
}
__device__ __forceinline__ unsigned long long pack2(float a){
    unsigned long long r; asm("mov.b64 %0, {%1, %1};" : "=l"(r) : "f"(a)); return r;
}
__device__ __forceinline__ unsigned long long pack2f(float a, float b){
    unsigned long long r; asm("mov.b64 %0, {%1, %2};" : "=l"(r) : "f"(a), "f"(b)); return r;
}
__device__ __forceinline__ void ffma2(unsigned long long& d, unsigned long long a, unsigned long long b){
    asm("fma.rn.f32x2 %0, %1, %2, %0;" : "+l"(d) : "l"(a), "l"(b));
}
__device__ __forceinline__ float2 unpack2(unsigned long long v){
    float2 r; asm("mov.b64 {%0, %1}, %2;" : "=f"(r.x), "=f"(r.y) : "l"(v)); return r;
}

// ---------------- prep: split x into bf16 hi/lo ----------------
__global__ __launch_bounds__(256) void k_split_x(const float* __restrict__ x){
    size_t i0 = ((size_t)blockIdx.x*256 + threadIdx.x)*8;
    float4 a = *(const float4*)(x + i0);
    float4 b4 = *(const float4*)(x + i0 + 4);
    float v[8] = {a.x,a.y,a.z,a.w,b4.x,b4.y,b4.z,b4.w};
    unsigned hb[8], lb[8];
    #pragma unroll
    for (int j=0;j<8;++j){
        __nv_bfloat16 h = __float2bfloat16(v[j]);
        float r = v[j] - __bfloat162float(h);
        __nv_bfloat16 l = __float2bfloat16(r);
        hb[j] = (unsigned)__bfloat16_as_ushort(h);
        lb[j] = (unsigned)__bfloat16_as_ushort(l);
    }
    uint4 ph = make_uint4(hb[0]|(hb[1]<<16), hb[2]|(hb[3]<<16), hb[4]|(hb[5]<<16), hb[6]|(hb[7]<<16));
    uint4 pl = make_uint4(lb[0]|(lb[1]<<16), lb[2]|(lb[3]<<16), lb[4]|(lb[5]<<16), lb[6]|(lb[7]<<16));
    *(uint4*)(&g_xhi[i0]) = ph;
    *(uint4*)(&g_xlo[i0]) = pl;
}

// ---------------- prep: transpose+split conv_w -> [oc][tap*256+ic] bf16 hi/lo ----------------
__global__ __launch_bounds__(256) void k_split_w(const float* __restrict__ cw){
    int oc = blockIdx.x;
    const float* src = cw + (size_t)oc*KTOT;   // [ic][27]
    for (int j=0;j<27;++j){
        int k = j*256 + threadIdx.x;           // tap=j, ic=tid
        float v = src[threadIdx.x*27 + j];
        __nv_bfloat16 h = __float2bfloat16(v);
        __nv_bfloat16 l = __float2bfloat16(v - __bfloat162float(h));
        g_whi[(size_t)oc*KTOT + k] = h;
        g_wlo[(size_t)oc*KTOT + k] = l;
    }
}

// ---------------- K init: max accumulators ----------------
__global__ void k_init_max(){
    int i = blockIdx.x*256 + threadIdx.x;
    if (i < NB*HEADS*G) g_max[i] = fenc(-3.4e38f);
}

// ---------------- K1: conv as mma.sync bf16 implicit GEMM (split both, 3 MMAs) ----------------
// CTA 128n x 128oc, 8 warps (warp tile 32x64), 2-stage pipeline, 2 CTAs/SM.
// Finest-grain interleave: ldmatrix pairs woven between 8-MMA sub-blocks so no
// more than 4 ldm4s ever precede an MMA group.
__global__ __launch_bounds__(256,2) void k1_conv_mma(const float* __restrict__ cb){
    extern __shared__ __align__(16) char sm[];
    __shared__ float s_bias[TN];
    const int tid = threadIdx.x;
    const int b = blockIdx.z, n0 = blockIdx.x*TM, oc0 = blockIdx.y*TN;
    if (tid < TN) s_bias[tid] = cb[oc0 + tid];

    const uint32_t s0 = smem_u32(sm);

    // ---- loader roles: 2 threads per row for both A (128 n-rows) and B (128 oc-rows)
    const int rowL = tid >> 1, half = tid & 1;
    const int nA = n0 + rowL;
    const int hA = nA >> 10, wA = (nA >> 5) & 31, dA = nA & 31;
    const __nv_bfloat16* xh_row = g_xhi + (size_t)b*NPTS*CIN + (size_t)nA*CIN + half*16;
    const __nv_bfloat16* xl_row = g_xlo + (size_t)b*NPTS*CIN + (size_t)nA*CIN + half*16;
    const uint32_t dstA = s0 + (uint32_t)rowL*80u + (uint32_t)half*32u;
    const __nv_bfloat16* wh_row = g_whi + (size_t)(oc0 + rowL)*KTOT + half*16;
    const __nv_bfloat16* wl_row = g_wlo + (size_t)(oc0 + rowL)*KTOT + half*16;
    const uint32_t dstB = s0 + 20480u + (uint32_t)rowL*80u + (uint32_t)half*32u;

    int cur_tap = -1;
    ptrdiff_t tap_off = 0;
    int tap_ss = 0;

    auto load_A = [&](int c, int buf){
        uint32_t bo = (uint32_t)buf * STAGE_BYTES;
        int tap = c >> 3;
        if (tap != cur_tap){
            cur_tap = tap;
            int dh = tap/9 - 1, dw = (tap/3)%3 - 1, dd = tap%3 - 1;
            bool valid = ((unsigned)(hA+dh) < 32u) && ((unsigned)(wA+dw) < 32u) && ((unsigned)(dA+dd) < 32u);
            tap_off = valid ? (ptrdiff_t)(dh*1024 + dw*32 + dd)*CIN : 0;
            tap_ss  = valid ? 16 : 0;
        }
        int ic0 = (c & 7) * 32;
        const __nv_bfloat16* sh = xh_row + tap_off + ic0;
        const __nv_bfloat16* sl = xl_row + tap_off + ic0;
        cp16(dstA + bo,           sh,     tap_ss);
        cp16(dstA + bo + 16,      sh + 8, tap_ss);
        cp16(dstA + bo + 10240,   sl,     tap_ss);
        cp16(dstA + bo + 10256,   sl + 8, tap_ss);
    };
    auto load_B = [&](int c, int buf){
        uint32_t bo = (uint32_t)buf * STAGE_BYTES;
        const __nv_bfloat16* bh = wh_row + (size_t)c*32;
        const __nv_bfloat16* bl = wl_row + (size_t)c*32;
        cp16(dstB + bo,           bh,     16);
        cp16(dstB + bo + 16,      bh + 8, 16);
        cp16(dstB + bo + 10240,   bl,     16);
        cp16(dstB + bo + 10256,   bl + 8, 16);
    };

    // ---- compute role: 8 warps, wm in {0,32,64,96}, wn in {0,64}
    const int lane = tid & 31, wid = tid >> 5;
    const int wm = (wid & 3) * 32;
    const int wn = (wid >> 2) * 64;
    const uint32_t ldA = s0 + (uint32_t)(wm + (lane & 15))*80u + (uint32_t)((lane >> 4) * 16);
    const uint32_t ldB = s0 + 20480u + (uint32_t)(wn + (lane & 15))*80u + (uint32_t)((lane >> 4) * 16);

    float acc[2][8][4];
    #pragma unroll
    for (int mi=0; mi<2; ++mi)
        #pragma unroll
        for (int ni=0; ni<8; ++ni){
            acc[mi][ni][0]=0.f; acc[mi][ni][1]=0.f; acc[mi][ni][2]=0.f; acc[mi][ni][3]=0.f;
        }

    load_A(0, 0); load_B(0, 0);
    asm volatile("cp.async.commit_group;");

    for (int c=0; c<NCHUNK; ++c){
        asm volatile("cp.async.wait_group 0;");
        __syncthreads();
        uint32_t bo = (uint32_t)(c & 1) * STAGE_BYTES;
        #pragma unroll
        for (int ks=0; ks<2; ++ks){
            uint32_t ko = (uint32_t)ks * 32u;   // 16 bf16 = 32 bytes
            unsigned ah[2][4], al[2][4], bh2[4][4], bl2[4][4];
            // minimal pre-MMA burst: ah + first half of bh
            ldm4(ah[0], ldA + bo + ko);
            ldm4(ah[1], ldA + bo + ko + 16*80);
            ldm4(bh2[0], ldB + bo + ko);
            ldm4(bh2[1], ldB + bo + ko + 16*80);
            // hh for nb=0,1 (8 MMAs)
            #pragma unroll
            for (int mi=0; mi<2; ++mi)
                #pragma unroll
                for (int nb=0; nb<2; ++nb){
                    mma_bf(acc[mi][2*nb],   ah[mi], bh2[nb][0], bh2[nb][2]);
                    mma_bf(acc[mi][2*nb+1], ah[mi], bh2[nb][1], bh2[nb][3]);
                }
            ldm4(bh2[2], ldB + bo + ko + 2*16*80);
            ldm4(bh2[3], ldB + bo + ko + 3*16*80);
            // hh for nb=2,3
            #pragma unroll
            for (int mi=0; mi<2; ++mi)
                #pragma unroll
                for (int nb=2; nb<4; ++nb){
                    mma_bf(acc[mi][2*nb],   ah[mi], bh2[nb][0], bh2[nb][2]);
                    mma_bf(acc[mi][2*nb+1], ah[mi], bh2[nb][1], bh2[nb][3]);
                }
            // prefetch under cover of hh MMAs
            if (ks == 0){
                if (c + 1 < NCHUNK) load_A(c + 1, (c + 1) & 1);
            } else {
                if (c + 1 < NCHUNK) load_B(c + 1, (c + 1) & 1);
                asm volatile("cp.async.commit_group;");
            }
            // lo fragments, first half
            ldm4(al[0], ldA + bo + ko + 10240);
            ldm4(al[1], ldA + bo + ko + 10240 + 16*80);
            ldm4(bl2[0], ldB + bo + ko + 10240);
            ldm4(bl2[1], ldB + bo + ko + 10240 + 16*80);
            // hl for nb=0,1
            #pragma unroll
            for (int mi=0; mi<2; ++mi)
                #pragma unroll
                for (int nb=0; nb<2; ++nb){
                    mma_bf(acc[mi][2*nb],   ah[mi], bl2[nb][0], bl2[nb][2]);
                    mma_bf(acc[mi][2*nb+1], ah[mi], bl2[nb][1], bl2[nb][3]);
                }
            ldm4(bl2[2], ldB + bo + ko + 10240 + 2*16*80);
            ldm4(bl2[3], ldB + bo + ko + 10240 + 3*16*80);
            // hl for nb=2,3
            #pragma unroll
            for (int mi=0; mi<2; ++mi)
                #pragma unroll
                for (int nb=2; nb<4; ++nb){
                    mma_bf(acc[mi][2*nb],   ah[mi], bl2[nb][0], bl2[nb][2]);
                    mma_bf(acc[mi][2*nb+1], ah[mi], bl2[nb][1], bl2[nb][3]);
                }
            // lh block (all fragments resident)
            #pragma unroll
            for (int mi=0; mi<2; ++mi)
                #pragma unroll
                for (int nb=0; nb<4; ++nb){
                    mma_bf(acc[mi][2*nb],   al[mi], bh2[nb][0], bh2[nb][2]);
                    mma_bf(acc[mi][2*nb+1], al[mi], bh2[nb][1], bh2[nb][3]);
                }
        }
    }

    // ---- epilogue: regs -> gmem with bias ----
    const int gid = lane >> 2, tig = lane & 3;
    #pragma unroll
    for (int mi=0; mi<2; ++mi){
        int row = n0 + wm + mi*16 + gid;
        float* rp = g_xp + ((size_t)b*NPTS + row)*CINNER + oc0;
        #pragma unroll
        for (int ni=0; ni<8; ++ni){
            int lc = wn + ni*8 + tig*2;
            float b0 = s_bias[lc], b1 = s_bias[lc+1];
            float2 v0 = make_float2(acc[mi][ni][0]+b0, acc[mi][ni][1]+b1);
            float2 v1 = make_float2(acc[mi][ni][2]+b0, acc[mi][ni][3]+b1);
            *(float2*)(rp + lc) = v0;
            *(float2*)(rp + lc + 8*CINNER) = v1;
        }
    }
}

// ---------------- K2: temp + scaled logits (c4-outer loop) ----------------
__global__ __launch_bounds__(256) void k2_logits(const float* __restrict__ slw, const float* __restrict__ slb,
                                                 const float* __restrict__ adw, const float* __restrict__ adb){
    __shared__ float xs[64][68];
    __shared__ float wsm[32][72];
    __shared__ float sb[32];
    __shared__ float temps[64];
    __shared__ float mred[256];
    int tid = threadIdx.x;
    int b = blockIdx.z, h = blockIdx.y, n0 = blockIdx.x*64;
    for (int i=tid; i<2048; i+=256) wsm[i>>6][i&63] = slw[i];
    if (tid < 32) sb[tid] = slb[tid];
    const float* xpb = g_xp + ((size_t)b*NPTS + n0)*CINNER + h*DHD;
    for (int i=tid; i<1024; i+=256){
        int r = i>>4, c4 = i&15;
        *(float4*)&xs[r][c4*4] = *(const float4*)(xpb + (size_t)r*CINNER + c4*4);
    }
    __syncthreads();
    if (tid < 64){
        float s = adb[0];
        #pragma unroll 8
        for (int c=0;c<64;++c) s += xs[tid][c]*adw[c];
        s = fminf(fmaxf(s, -0.4f), 0.4f);
        temps[tid] = 1.0f/(0.5f + s);
    }
    __syncthreads();
    const float LLNE = logf(-logf(1e-6f));
    int g = tid>>3, ns = tid&7;
    float sacc[8] = {0.f,0.f,0.f,0.f,0.f,0.f,0.f,0.f};
    #pragma unroll
    for (int c4=0;c4<16;++c4){
        float4 wv = *(const float4*)&wsm[g][c4*4];
        #pragma unroll
        for (int i=0;i<8;++i){
            float4 xv = *(const float4*)&xs[ns + i*8][c4*4];
            sacc[i] += xv.x*wv.x + xv.y*wv.y + xv.z*wv.z + xv.w*wv.w;
        }
    }
    float lmax = -3.4e38f;
    float* lout = g_l + ((size_t)(b*HEADS+h)*G + g)*NPTS + n0;
    #pragma unroll
    for (int i=0;i<8;++i){
        int nn = ns + i*8;
        float l = (sacc[i] + sb[g] - LLNE)*temps[nn];
        lout[nn] = l;
        lmax = fmaxf(lmax, l);
    }
    mred[tid] = lmax;
    __syncthreads();
    if (ns == 0){
        float m = mred[tid];
        #pragma unroll
        for (int j=1;j<8;++j) m = fmaxf(m, mred[tid+j]);
        atomicMax(&g_max[(b*HEADS+h)*G + g], fenc(m));
    }
}

// ---------------- K3: exp in place + partial denom sums ----------------
__global__ __launch_bounds__(256) void k3_exp(){
    __shared__ float red[256];
    int tid = threadIdx.x;
    int chunk = blockIdx.x, bhg = blockIdx.y;
    float m = fdec(g_max[bhg]);
    size_t base = (size_t)bhg*NPTS + (size_t)chunk*2048;
    float s = 0.f;
    #pragma unroll
    for (int i=0;i<8;++i){
        size_t idx = base + tid + i*256;
        float e = expf(g_l[idx] - m);
        g_l[idx] = e;
        s += e;
    }
    red[tid]=s; __syncthreads();
    for (int off=128; off>0; off>>=1){ if (tid<off) red[tid]+=red[tid+off]; __syncthreads(); }
    if (tid==0) g_denom_part[bhg*16 + chunk] = red[0];
}
__global__ void k3b_denom(){
    int i = blockIdx.x*256 + threadIdx.x;   // bhg
    float s = 0.f;
    #pragma unroll
    for (int c=0;c<16;++c) s += g_denom_part[i*16+c];
    g_denom[i] = s;
}

// ---------------- K5: eid partials (split-K GEMM, FFMA2 packed) ----------------
__global__ __launch_bounds__(256) void k5_eid_part(){
    __shared__ float xs[64][64];
    __shared__ float es[32][68];
    int tid = threadIdx.x;
    int chunk = blockIdx.x, bh = blockIdx.y;
    int b = bh>>3, h = bh&7;
    int g = tid>>3, cb2 = (tid&7)*8;
    unsigned long long acc2[4] = {0ULL,0ULL,0ULL,0ULL};
    for (int t=0; t<32; ++t){
        int n0 = chunk*2048 + t*64;
        __syncthreads();
        const float* xpb = g_xp + ((size_t)b*NPTS + n0)*CINNER + h*DHD;
        #pragma unroll
        for (int i=0;i<4;++i){
            int idx = tid + i*256;
            int r = idx>>4, c4 = idx&15;
            *(float4*)&xs[r][c4*4] = *(const float4*)(xpb + (size_t)r*CINNER + c4*4);
        }
        const float* lb = g_l + ((size_t)bh*G)*NPTS + n0;
        #pragma unroll
        for (int i=0;i<2;++i){
            int idx = tid + i*256;
            int r = idx>>4, c4 = idx&15;
            *(float4*)&es[r][c4*4] = *(const float4*)(lb + (size_t)r*NPTS + c4*4);
        }
        __syncthreads();
        #pragma unroll 4
        for (int n=0;n<64;++n){
            unsigned long long ev2 = pack2(es[g][n]);
            ulonglong2 x01 = *(const ulonglong2*)&xs[n][cb2];
            ulonglong2 x23 = *(const ulonglong2*)&xs[n][cb2+4];
            ffma2(acc2[0], ev2, x01.x);
            ffma2(acc2[1], ev2, x01.y);
            ffma2(acc2[2], ev2, x23.x);
            ffma2(acc2[3], ev2, x23.y);
        }
    }
    float* dst = g_eid_part + (size_t)(bh*16+chunk)*2048 + g*64 + cb2;
    #pragma unroll
    for (int j=0;j<4;++j){
        float2 p = unpack2(acc2[j]);
        dst[2*j]   = p.x;
        dst[2*j+1] = p.y;
    }
}
__global__ void k5b_eid(){
    int bh = blockIdx.x;
    int tid = threadIdx.x;
    #pragma unroll
    for (int j=0;j<8;++j){
        int s = tid + j*256;
        float acc = 0.f;
        #pragma unroll
        for (int ch=0; ch<16; ++ch) acc += g_eid_part[(size_t)(bh*16+ch)*2048 + s];
        float dn = g_denom[bh*G + (s>>6)];
        g_eid[(size_t)bh*2048 + s] = acc / (dn * (1.0f + 1e-5f));
    }
}

// ---------------- K6: proj[b][hg][o] = (eid @ out_w_slice^T) / denom ----------------
__global__ __launch_bounds__(256) void k6_proj(const float* __restrict__ ow){
    __shared__ float ev[64];
    int b = blockIdx.y, k = blockIdx.x;
    int h = k>>5, g = k&31;
    int tid = threadIdx.x;    // = o
    if (tid < 64) ev[tid] = g_eid[(size_t)(b*8+h)*2048 + g*64 + tid];
    __syncthreads();
    const float* wr = ow + (size_t)tid*CINNER + h*DHD;
    float s = 0.f;
    #pragma unroll 8
    for (int c=0;c<64;++c) s += ev[c]*wr[c];
    g_proj[((size_t)b*256 + k)*256 + tid] = s / g_denom[(b*8+h)*G + g];
}

// ---------------- K7: final = E^T(256,N) x proj(256,256) + out_b (FFMA2 packed) ----------------
__global__ __launch_bounds__(256) void k7_final(const float* __restrict__ ob, float* __restrict__ out){
    __shared__ float as2[16][132];
    __shared__ float ps[16][68];
    int tid = threadIdx.x;
    int b = blockIdx.z, n0 = blockIdx.x*128, o0 = blockIdx.y*64;
    int mf = tid&15, of = tid>>4;
    unsigned long long acc2[8][2];
    #pragma unroll
    for (int i=0;i<8;++i){ acc2[i][0]=0ULL; acc2[i][1]=0ULL; }
    for (int kt=0; kt<16; ++kt){
        int k0 = kt*16;
        __syncthreads();
        #pragma unroll
        for (int i=0;i<2;++i){
            int idx = tid + i*256;
            int r = idx>>5, c4 = idx&31;
            *(float4*)&as2[r][c4*4] = *(const float4*)(g_l + ((size_t)b*256 + k0 + r)*NPTS + n0 + c4*4);
        }
        {
            int r = tid>>4, c4 = tid&15;
            *(float4*)&ps[r][c4*4] = *(const float4*)(g_proj + ((size_t)b*256 + k0 + r)*256 + o0 + c4*4);
        }
        __syncthreads();
        #pragma unroll
        for (int kk=0;kk<16;++kk){
            float4 a0 = *(const float4*)&as2[kk][mf*8];
            float4 a1 = *(const float4*)&as2[kk][mf*8+4];
            float4 bv = *(const float4*)&ps[kk][of*4];
            unsigned long long b01 = pack2f(bv.x, bv.y);
            unsigned long long b23 = pack2f(bv.z, bv.w);
            float av[8]={a0.x,a0.y,a0.z,a0.w,a1.x,a1.y,a1.z,a1.w};
            #pragma unroll
            for (int i=0;i<8;++i){
                unsigned long long ap = pack2(av[i]);
                ffma2(acc2[i][0], ap, b01);
                ffma2(acc2[i][1], ap, b23);
            }
        }
    }
    float obv[4];
    #pragma unroll
    for (int j=0;j<4;++j) obv[j] = ob[o0 + of*4 + j];
    #pragma unroll
    for (int i=0;i<8;++i){
        int n = n0 + mf*8 + i;
        float2 p0 = unpack2(acc2[i][0]);
        float2 p1 = unpack2(acc2[i][1]);
        *(float4*)(out + ((size_t)b*NPTS + n)*256 + o0 + of*4) =
            make_float4(p0.x+obv[0], p0.y+obv[1], p1.x+obv[2], p1.y+obv[3]);
    }
}

// ---------------- launch ----------------
extern "C" void kernel_launch(void* const* d_in, const int* in_sizes, int n_in,
                              void* d_out, int out_size){
    const float* x   = (const float*)d_in[0];
    const float* cw  = (const float*)d_in[1];
    const float* cb  = (const float*)d_in[2];
    const float* slw = (const float*)d_in[3];
    const float* slb = (const float*)d_in[4];
    const float* adw = (const float*)d_in[5];
    const float* adb = (const float*)d_in[6];
    const float* ow  = (const float*)d_in[7];
    const float* ob  = (const float*)d_in[8];
    float* out = (float*)d_out;

    cudaFuncSetAttribute(k1_conv_mma, cudaFuncAttributeMaxDynamicSharedMemorySize, STAGES*STAGE_BYTES);

    k_split_x  <<<16384, 256>>>(x);
    k_split_w  <<<512, 256>>>(cw);
    k_init_max <<<4, 256>>>();
    k1_conv_mma<<<dim3(256,4,4), 256, STAGES*STAGE_BYTES>>>(cb);   // launch idx 3 -> profiled
    k2_logits  <<<dim3(512,8,4), 256>>>(slw, slb, adw, adb);
    k3_exp     <<<dim3(16,1024), 256>>>();
    k3b_denom  <<<4, 256>>>();
    k5_eid_part<<<dim3(16,32), 256>>>();
    k5b_eid    <<<32, 256>>>();
    k6_proj    <<<dim3(256,4), 256>>>(ow);
    k7_final   <<<dim3(256,4,4), 256>>>(ob, out);
}